// round 3
// baseline (speedup 1.0000x reference)
#include <cuda_runtime.h>
#include <math.h>
#include <stdint.h>

// Problem constants
#define T_TOK 2048
#define D_MODEL 1024
#define D_FF 4096
#define N_EXP 8

// ---------------- static scratch (no allocations allowed) ----------------
// H: per-expert activation rows, capacity T_TOK rows per expert (a token can
// appear at most once per expert since top-k indices are distinct).
__device__ float g_H[(size_t)N_EXP * T_TOK * D_FF];      // 256 MB
__device__ float g_Y[(size_t)2 * T_TOK * D_MODEL];       // 16 MB, indexed by assignment id
__device__ int   g_alist[N_EXP * T_TOK];                 // assignment id = tok*2 + slot
__device__ float g_wlist[N_EXP * T_TOK];                 // routing weight per assignment
__device__ int   g_count[N_EXP];

// ---------------- reset ----------------
__global__ void zero_counts_kernel() {
    int i = threadIdx.x;
    if (i < N_EXP) g_count[i] = 0;
}

// ---------------- gating: logits, top-2, softmax, build lists ----------------
__global__ void gate_kernel(const float* __restrict__ x,
                            const float* __restrict__ wg,
                            const float* __restrict__ bg) {
    int warp = (blockIdx.x * blockDim.x + threadIdx.x) >> 5;
    int lane = threadIdx.x & 31;
    if (warp >= T_TOK) return;

    const float* xr = x + (size_t)warp * D_MODEL;
    float acc[N_EXP];
#pragma unroll
    for (int e = 0; e < N_EXP; e++) acc[e] = 0.f;

    for (int d = lane; d < D_MODEL; d += 32) {
        float xv = xr[d];
        const float* wr = wg + (size_t)d * N_EXP;
#pragma unroll
        for (int e = 0; e < N_EXP; e++) acc[e] += xv * wr[e];
    }
#pragma unroll
    for (int e = 0; e < N_EXP; e++) {
#pragma unroll
        for (int off = 16; off > 0; off >>= 1)
            acc[e] += __shfl_xor_sync(0xFFFFFFFFu, acc[e], off);
    }

    if (lane == 0) {
        float v[N_EXP];
#pragma unroll
        for (int e = 0; e < N_EXP; e++) v[e] = acc[e] + bg[e];
        // top-1 (lowest index wins ties, matching lax.top_k)
        int i0 = 0;
#pragma unroll
        for (int e = 1; e < N_EXP; e++) if (v[e] > v[i0]) i0 = e;
        // top-2
        int i1 = (i0 == 0) ? 1 : 0;
#pragma unroll
        for (int e = 0; e < N_EXP; e++)
            if (e != i0 && v[e] > v[i1]) i1 = e;

        // softmax over the two selected logits (v[i0] >= v[i1])
        float w0 = 1.0f / (1.0f + expf(v[i1] - v[i0]));
        float w1 = 1.0f - w0;

        int p0 = atomicAdd(&g_count[i0], 1);
        g_alist[i0 * T_TOK + p0] = warp * 2 + 0;
        g_wlist[i0 * T_TOK + p0] = w0;
        int p1 = atomicAdd(&g_count[i1], 1);
        g_alist[i1 * T_TOK + p1] = warp * 2 + 1;
        g_wlist[i1 * T_TOK + p1] = w1;
    }
}

// ---------------- tiled SGEMM constants ----------------
#define BM 128
#define BN 128
#define BK 8

// GEMM1: H[e,pos,:] = relu( X[tok(pos),:] @ w1[e] + b1[e] )
__global__ __launch_bounds__(256) void gemm1_kernel(
    const float* __restrict__ x,
    const float* __restrict__ w1,
    const float* __restrict__ b1) {
    int e = blockIdx.z;
    int cnt = g_count[e];
    int m0 = blockIdx.y * BM;
    if (m0 >= cnt) return;
    int n0 = blockIdx.x * BN;

    __shared__ float As[BK][BM + 4];
    __shared__ float Bs[BK][BN];

    int tid = threadIdx.x;
    int a_row = tid >> 1;
    int a_k4  = (tid & 1) * 4;
    int b_k   = tid >> 5;
    int b_n4  = (tid & 31) * 4;

    int am = m0 + a_row;
    int tok = (am < cnt) ? (g_alist[e * T_TOK + am] >> 1) : 0;
    const float* Arow = x + (size_t)tok * D_MODEL;
    const float* Bbase = w1 + (size_t)e * D_MODEL * D_FF + n0;

    int ty = tid >> 4, tx = tid & 15;
    float acc[8][8];
#pragma unroll
    for (int i = 0; i < 8; i++)
#pragma unroll
        for (int j = 0; j < 8; j++) acc[i][j] = 0.f;

    for (int k0 = 0; k0 < D_MODEL; k0 += BK) {
        float4 av = *(const float4*)(Arow + k0 + a_k4);
        As[a_k4 + 0][a_row] = av.x;
        As[a_k4 + 1][a_row] = av.y;
        As[a_k4 + 2][a_row] = av.z;
        As[a_k4 + 3][a_row] = av.w;
        *(float4*)(&Bs[b_k][b_n4]) =
            *(const float4*)(Bbase + (size_t)(k0 + b_k) * D_FF + b_n4);
        __syncthreads();
#pragma unroll
        for (int k = 0; k < BK; k++) {
            float a[8], b[8];
#pragma unroll
            for (int i = 0; i < 8; i++) a[i] = As[k][ty * 8 + i];
#pragma unroll
            for (int j = 0; j < 8; j++) b[j] = Bs[k][tx * 8 + j];
#pragma unroll
            for (int i = 0; i < 8; i++)
#pragma unroll
                for (int j = 0; j < 8; j++) acc[i][j] += a[i] * b[j];
        }
        __syncthreads();
    }

    const float* b1e = b1 + (size_t)e * D_FF + n0 + tx * 8;
    float bb[8];
#pragma unroll
    for (int j = 0; j < 8; j++) bb[j] = b1e[j];

#pragma unroll
    for (int i = 0; i < 8; i++) {
        int row = m0 + ty * 8 + i;
        if (row < cnt) {
            float* Hp = g_H + ((size_t)e * T_TOK + row) * D_FF + n0 + tx * 8;
            float4 v0, v1;
            float t0 = acc[i][0] + bb[0]; v0.x = t0 > 0.f ? t0 : 0.f;
            float t1 = acc[i][1] + bb[1]; v0.y = t1 > 0.f ? t1 : 0.f;
            float t2 = acc[i][2] + bb[2]; v0.z = t2 > 0.f ? t2 : 0.f;
            float t3 = acc[i][3] + bb[3]; v0.w = t3 > 0.f ? t3 : 0.f;
            float t4 = acc[i][4] + bb[4]; v1.x = t4 > 0.f ? t4 : 0.f;
            float t5 = acc[i][5] + bb[5]; v1.y = t5 > 0.f ? t5 : 0.f;
            float t6 = acc[i][6] + bb[6]; v1.z = t6 > 0.f ? t6 : 0.f;
            float t7 = acc[i][7] + bb[7]; v1.w = t7 > 0.f ? t7 : 0.f;
            *(float4*)(Hp + 0) = v0;
            *(float4*)(Hp + 4) = v1;
        }
    }
}

// GEMM2: Y[a,:] = w_a * ( H[e,pos,:] @ w2[e] + b2[e] )
__global__ __launch_bounds__(256) void gemm2_kernel(
    const float* __restrict__ w2,
    const float* __restrict__ b2) {
    int e = blockIdx.z;
    int cnt = g_count[e];
    int m0 = blockIdx.y * BM;
    if (m0 >= cnt) return;
    int n0 = blockIdx.x * BN;

    __shared__ float As[BK][BM + 4];
    __shared__ float Bs[BK][BN];

    int tid = threadIdx.x;
    int a_row = tid >> 1;
    int a_k4  = (tid & 1) * 4;
    int b_k   = tid >> 5;
    int b_n4  = (tid & 31) * 4;

    int am = m0 + a_row;
    int arow_clamped = (am < cnt) ? am : 0;
    const float* Arow = g_H + ((size_t)e * T_TOK + arow_clamped) * D_FF;
    const float* Bbase = w2 + (size_t)e * D_FF * D_MODEL + n0;

    int ty = tid >> 4, tx = tid & 15;
    float acc[8][8];
#pragma unroll
    for (int i = 0; i < 8; i++)
#pragma unroll
        for (int j = 0; j < 8; j++) acc[i][j] = 0.f;

    for (int k0 = 0; k0 < D_FF; k0 += BK) {
        float4 av = *(const float4*)(Arow + k0 + a_k4);
        As[a_k4 + 0][a_row] = av.x;
        As[a_k4 + 1][a_row] = av.y;
        As[a_k4 + 2][a_row] = av.z;
        As[a_k4 + 3][a_row] = av.w;
        *(float4*)(&Bs[b_k][b_n4]) =
            *(const float4*)(Bbase + (size_t)(k0 + b_k) * D_MODEL + b_n4);
        __syncthreads();
#pragma unroll
        for (int k = 0; k < BK; k++) {
            float a[8], b[8];
#pragma unroll
            for (int i = 0; i < 8; i++) a[i] = As[k][ty * 8 + i];
#pragma unroll
            for (int j = 0; j < 8; j++) b[j] = Bs[k][tx * 8 + j];
#pragma unroll
            for (int i = 0; i < 8; i++)
#pragma unroll
                for (int j = 0; j < 8; j++) acc[i][j] += a[i] * b[j];
        }
        __syncthreads();
    }

    const float* b2e = b2 + (size_t)e * D_MODEL + n0 + tx * 8;
    float bb[8];
#pragma unroll
    for (int j = 0; j < 8; j++) bb[j] = b2e[j];

#pragma unroll
    for (int i = 0; i < 8; i++) {
        int row = m0 + ty * 8 + i;
        if (row < cnt) {
            int a_id = g_alist[e * T_TOK + row];
            float wgt = g_wlist[e * T_TOK + row];
            float* Yp = g_Y + (size_t)a_id * D_MODEL + n0 + tx * 8;
            float4 v0, v1;
            v0.x = wgt * (acc[i][0] + bb[0]);
            v0.y = wgt * (acc[i][1] + bb[1]);
            v0.z = wgt * (acc[i][2] + bb[2]);
            v0.w = wgt * (acc[i][3] + bb[3]);
            v1.x = wgt * (acc[i][4] + bb[4]);
            v1.y = wgt * (acc[i][5] + bb[5]);
            v1.z = wgt * (acc[i][6] + bb[6]);
            v1.w = wgt * (acc[i][7] + bb[7]);
            *(float4*)(Yp + 0) = v0;
            *(float4*)(Yp + 4) = v1;
        }
    }
}

// ---------------- combine: out[t] = Y[2t] + Y[2t+1] ----------------
__global__ void combine_kernel(float* __restrict__ out) {
    int i = blockIdx.x * blockDim.x + threadIdx.x;  // over T_TOK * D_MODEL / 4
    int total = T_TOK * D_MODEL / 4;
    if (i >= total) return;
    int t = (i * 4) >> 10;  // token index (D_MODEL = 1024)
    const float4* y0 = (const float4*)(g_Y + (size_t)(2 * t) * D_MODEL) + (i & 255);
    const float4* y1 = (const float4*)(g_Y + (size_t)(2 * t + 1) * D_MODEL) + (i & 255);
    float4 a = *y0, b = *y1;
    float4 r;
    r.x = a.x + b.x; r.y = a.y + b.y; r.z = a.z + b.z; r.w = a.w + b.w;
    ((float4*)out)[i] = r;
}

// ---------------- launch ----------------
extern "C" void kernel_launch(void* const* d_in, const int* in_sizes, int n_in,
                              void* d_out, int out_size) {
    const float* x   = (const float*)d_in[0];  // [1,2048,1024]
    const float* wg  = (const float*)d_in[1];  // [1024,8]
    const float* bg  = (const float*)d_in[2];  // [8]
    const float* w1  = (const float*)d_in[3];  // [8,1024,4096]
    const float* b1  = (const float*)d_in[4];  // [8,4096]
    const float* w2  = (const float*)d_in[5];  // [8,4096,1024]
    const float* b2  = (const float*)d_in[6];  // [8,1024]
    float* out = (float*)d_out;

    zero_counts_kernel<<<1, 32>>>();
    // 2048 tokens, 1 warp each -> 256 blocks of 256 threads
    gate_kernel<<<(T_TOK * 32) / 256, 256>>>(x, wg, bg);

    dim3 g1(D_FF / BN, T_TOK / BM, N_EXP);   // 32 x 16 x 8
    gemm1_kernel<<<g1, 256>>>(x, w1, b1);

    dim3 g2(D_MODEL / BN, T_TOK / BM, N_EXP); // 8 x 16 x 8
    gemm2_kernel<<<g2, 256>>>(w2, b2);

    combine_kernel<<<(T_TOK * D_MODEL / 4 + 255) / 256, 256>>>(out);
}

// round 4
// speedup vs baseline: 1.0035x; 1.0035x over previous
#include <cuda_runtime.h>
#include <math.h>
#include <stdint.h>

// Problem constants
#define T_TOK 2048
#define D_MODEL 1024
#define D_FF 4096
#define N_EXP 8

// ---------------- static scratch (no allocations allowed) ----------------
// H: per-expert activation rows, capacity T_TOK rows per expert (a token can
// appear at most once per expert since top-k indices are distinct).
__device__ float g_H[(size_t)N_EXP * T_TOK * D_FF];      // 256 MB
__device__ float g_Y[(size_t)2 * T_TOK * D_MODEL];       // 16 MB, indexed by assignment id
__device__ int   g_alist[N_EXP * T_TOK];                 // assignment id = tok*2 + slot
__device__ float g_wlist[N_EXP * T_TOK];                 // routing weight per assignment
__device__ int   g_count[N_EXP];

// ---------------- reset ----------------
__global__ void zero_counts_kernel() {
    int i = threadIdx.x;
    if (i < N_EXP) g_count[i] = 0;
}

// ---------------- gating: logits, top-2, softmax, build lists ----------------
__global__ void gate_kernel(const float* __restrict__ x,
                            const float* __restrict__ wg,
                            const float* __restrict__ bg) {
    int warp = (blockIdx.x * blockDim.x + threadIdx.x) >> 5;
    int lane = threadIdx.x & 31;
    if (warp >= T_TOK) return;

    const float* xr = x + (size_t)warp * D_MODEL;
    float acc[N_EXP];
#pragma unroll
    for (int e = 0; e < N_EXP; e++) acc[e] = 0.f;

    for (int d = lane; d < D_MODEL; d += 32) {
        float xv = xr[d];
        const float* wr = wg + (size_t)d * N_EXP;
#pragma unroll
        for (int e = 0; e < N_EXP; e++) acc[e] += xv * wr[e];
    }
#pragma unroll
    for (int e = 0; e < N_EXP; e++) {
#pragma unroll
        for (int off = 16; off > 0; off >>= 1)
            acc[e] += __shfl_xor_sync(0xFFFFFFFFu, acc[e], off);
    }

    if (lane == 0) {
        float v[N_EXP];
#pragma unroll
        for (int e = 0; e < N_EXP; e++) v[e] = acc[e] + bg[e];
        // top-1 (lowest index wins ties, matching lax.top_k)
        int i0 = 0;
#pragma unroll
        for (int e = 1; e < N_EXP; e++) if (v[e] > v[i0]) i0 = e;
        // top-2
        int i1 = (i0 == 0) ? 1 : 0;
#pragma unroll
        for (int e = 0; e < N_EXP; e++)
            if (e != i0 && v[e] > v[i1]) i1 = e;

        // softmax over the two selected logits (v[i0] >= v[i1])
        float w0 = 1.0f / (1.0f + expf(v[i1] - v[i0]));
        float w1 = 1.0f - w0;

        int p0 = atomicAdd(&g_count[i0], 1);
        g_alist[i0 * T_TOK + p0] = warp * 2 + 0;
        g_wlist[i0 * T_TOK + p0] = w0;
        int p1 = atomicAdd(&g_count[i1], 1);
        g_alist[i1 * T_TOK + p1] = warp * 2 + 1;
        g_wlist[i1 * T_TOK + p1] = w1;
    }
}

// ---------------- tiled SGEMM constants ----------------
#define BM 128
#define BN 128
#define BK 8

// GEMM1: H[e,pos,:] = relu( X[tok(pos),:] @ w1[e] + b1[e] )
__global__ __launch_bounds__(256) void gemm1_kernel(
    const float* __restrict__ x,
    const float* __restrict__ w1,
    const float* __restrict__ b1) {
    int e = blockIdx.z;
    int cnt = g_count[e];
    int m0 = blockIdx.y * BM;
    if (m0 >= cnt) return;
    int n0 = blockIdx.x * BN;

    __shared__ float As[BK][BM + 4];
    __shared__ float Bs[BK][BN];

    int tid = threadIdx.x;
    int a_row = tid >> 1;
    int a_k4  = (tid & 1) * 4;
    int b_k   = tid >> 5;
    int b_n4  = (tid & 31) * 4;

    int am = m0 + a_row;
    int tok = (am < cnt) ? (g_alist[e * T_TOK + am] >> 1) : 0;
    const float* Arow = x + (size_t)tok * D_MODEL;
    const float* Bbase = w1 + (size_t)e * D_MODEL * D_FF + n0;

    int ty = tid >> 4, tx = tid & 15;
    float acc[8][8];
#pragma unroll
    for (int i = 0; i < 8; i++)
#pragma unroll
        for (int j = 0; j < 8; j++) acc[i][j] = 0.f;

    for (int k0 = 0; k0 < D_MODEL; k0 += BK) {
        float4 av = *(const float4*)(Arow + k0 + a_k4);
        As[a_k4 + 0][a_row] = av.x;
        As[a_k4 + 1][a_row] = av.y;
        As[a_k4 + 2][a_row] = av.z;
        As[a_k4 + 3][a_row] = av.w;
        *(float4*)(&Bs[b_k][b_n4]) =
            *(const float4*)(Bbase + (size_t)(k0 + b_k) * D_FF + b_n4);
        __syncthreads();
#pragma unroll
        for (int k = 0; k < BK; k++) {
            float a[8], b[8];
#pragma unroll
            for (int i = 0; i < 8; i++) a[i] = As[k][ty * 8 + i];
#pragma unroll
            for (int j = 0; j < 8; j++) b[j] = Bs[k][tx * 8 + j];
#pragma unroll
            for (int i = 0; i < 8; i++)
#pragma unroll
                for (int j = 0; j < 8; j++) acc[i][j] += a[i] * b[j];
        }
        __syncthreads();
    }

    const float* b1e = b1 + (size_t)e * D_FF + n0 + tx * 8;
    float bb[8];
#pragma unroll
    for (int j = 0; j < 8; j++) bb[j] = b1e[j];

#pragma unroll
    for (int i = 0; i < 8; i++) {
        int row = m0 + ty * 8 + i;
        if (row < cnt) {
            float* Hp = g_H + ((size_t)e * T_TOK + row) * D_FF + n0 + tx * 8;
            float4 v0, v1;
            float t0 = acc[i][0] + bb[0]; v0.x = t0 > 0.f ? t0 : 0.f;
            float t1 = acc[i][1] + bb[1]; v0.y = t1 > 0.f ? t1 : 0.f;
            float t2 = acc[i][2] + bb[2]; v0.z = t2 > 0.f ? t2 : 0.f;
            float t3 = acc[i][3] + bb[3]; v0.w = t3 > 0.f ? t3 : 0.f;
            float t4 = acc[i][4] + bb[4]; v1.x = t4 > 0.f ? t4 : 0.f;
            float t5 = acc[i][5] + bb[5]; v1.y = t5 > 0.f ? t5 : 0.f;
            float t6 = acc[i][6] + bb[6]; v1.z = t6 > 0.f ? t6 : 0.f;
            float t7 = acc[i][7] + bb[7]; v1.w = t7 > 0.f ? t7 : 0.f;
            *(float4*)(Hp + 0) = v0;
            *(float4*)(Hp + 4) = v1;
        }
    }
}

// GEMM2: Y[a,:] = w_a * ( H[e,pos,:] @ w2[e] + b2[e] )
__global__ __launch_bounds__(256) void gemm2_kernel(
    const float* __restrict__ w2,
    const float* __restrict__ b2) {
    int e = blockIdx.z;
    int cnt = g_count[e];
    int m0 = blockIdx.y * BM;
    if (m0 >= cnt) return;
    int n0 = blockIdx.x * BN;

    __shared__ float As[BK][BM + 4];
    __shared__ float Bs[BK][BN];

    int tid = threadIdx.x;
    int a_row = tid >> 1;
    int a_k4  = (tid & 1) * 4;
    int b_k   = tid >> 5;
    int b_n4  = (tid & 31) * 4;

    int am = m0 + a_row;
    int arow_clamped = (am < cnt) ? am : 0;
    const float* Arow = g_H + ((size_t)e * T_TOK + arow_clamped) * D_FF;
    const float* Bbase = w2 + (size_t)e * D_FF * D_MODEL + n0;

    int ty = tid >> 4, tx = tid & 15;
    float acc[8][8];
#pragma unroll
    for (int i = 0; i < 8; i++)
#pragma unroll
        for (int j = 0; j < 8; j++) acc[i][j] = 0.f;

    for (int k0 = 0; k0 < D_FF; k0 += BK) {
        float4 av = *(const float4*)(Arow + k0 + a_k4);
        As[a_k4 + 0][a_row] = av.x;
        As[a_k4 + 1][a_row] = av.y;
        As[a_k4 + 2][a_row] = av.z;
        As[a_k4 + 3][a_row] = av.w;
        *(float4*)(&Bs[b_k][b_n4]) =
            *(const float4*)(Bbase + (size_t)(k0 + b_k) * D_MODEL + b_n4);
        __syncthreads();
#pragma unroll
        for (int k = 0; k < BK; k++) {
            float a[8], b[8];
#pragma unroll
            for (int i = 0; i < 8; i++) a[i] = As[k][ty * 8 + i];
#pragma unroll
            for (int j = 0; j < 8; j++) b[j] = Bs[k][tx * 8 + j];
#pragma unroll
            for (int i = 0; i < 8; i++)
#pragma unroll
                for (int j = 0; j < 8; j++) acc[i][j] += a[i] * b[j];
        }
        __syncthreads();
    }

    const float* b2e = b2 + (size_t)e * D_MODEL + n0 + tx * 8;
    float bb[8];
#pragma unroll
    for (int j = 0; j < 8; j++) bb[j] = b2e[j];

#pragma unroll
    for (int i = 0; i < 8; i++) {
        int row = m0 + ty * 8 + i;
        if (row < cnt) {
            int a_id = g_alist[e * T_TOK + row];
            float wgt = g_wlist[e * T_TOK + row];
            float* Yp = g_Y + (size_t)a_id * D_MODEL + n0 + tx * 8;
            float4 v0, v1;
            v0.x = wgt * (acc[i][0] + bb[0]);
            v0.y = wgt * (acc[i][1] + bb[1]);
            v0.z = wgt * (acc[i][2] + bb[2]);
            v0.w = wgt * (acc[i][3] + bb[3]);
            v1.x = wgt * (acc[i][4] + bb[4]);
            v1.y = wgt * (acc[i][5] + bb[5]);
            v1.z = wgt * (acc[i][6] + bb[6]);
            v1.w = wgt * (acc[i][7] + bb[7]);
            *(float4*)(Yp + 0) = v0;
            *(float4*)(Yp + 4) = v1;
        }
    }
}

// ---------------- combine: out[t] = Y[2t] + Y[2t+1] ----------------
__global__ void combine_kernel(float* __restrict__ out) {
    int i = blockIdx.x * blockDim.x + threadIdx.x;  // over T_TOK * D_MODEL / 4
    int total = T_TOK * D_MODEL / 4;
    if (i >= total) return;
    int t = (i * 4) >> 10;  // token index (D_MODEL = 1024)
    const float4* y0 = (const float4*)(g_Y + (size_t)(2 * t) * D_MODEL) + (i & 255);
    const float4* y1 = (const float4*)(g_Y + (size_t)(2 * t + 1) * D_MODEL) + (i & 255);
    float4 a = *y0, b = *y1;
    float4 r;
    r.x = a.x + b.x; r.y = a.y + b.y; r.z = a.z + b.z; r.w = a.w + b.w;
    ((float4*)out)[i] = r;
}

// ---------------- launch ----------------
extern "C" void kernel_launch(void* const* d_in, const int* in_sizes, int n_in,
                              void* d_out, int out_size) {
    const float* x   = (const float*)d_in[0];  // [1,2048,1024]
    const float* wg  = (const float*)d_in[1];  // [1024,8]
    const float* bg  = (const float*)d_in[2];  // [8]
    const float* w1  = (const float*)d_in[3];  // [8,1024,4096]
    const float* b1  = (const float*)d_in[4];  // [8,4096]
    const float* w2  = (const float*)d_in[5];  // [8,4096,1024]
    const float* b2  = (const float*)d_in[6];  // [8,1024]
    float* out = (float*)d_out;

    zero_counts_kernel<<<1, 32>>>();
    // 2048 tokens, 1 warp each -> 256 blocks of 256 threads
    gate_kernel<<<(T_TOK * 32) / 256, 256>>>(x, wg, bg);

    dim3 g1(D_FF / BN, T_TOK / BM, N_EXP);   // 32 x 16 x 8
    gemm1_kernel<<<g1, 256>>>(x, w1, b1);

    dim3 g2(D_MODEL / BN, T_TOK / BM, N_EXP); // 8 x 16 x 8
    gemm2_kernel<<<g2, 256>>>(w2, b2);

    combine_kernel<<<(T_TOK * D_MODEL / 4 + 255) / 256, 256>>>(out);
}

// round 6
// speedup vs baseline: 3.5398x; 3.5275x over previous
#include <cuda_runtime.h>
#include <math.h>
#include <stdint.h>

#define T_TOK 2048
#define D_MODEL 1024
#define D_FF 4096
#define N_EXP 8

// ---------------- static scratch (no allocations allowed) ----------------
__device__ float g_H[(size_t)N_EXP * T_TOK * D_FF];      // row-major [e][pos][ff]
__device__ float g_Xg[(size_t)N_EXP * T_TOK * D_MODEL];  // gathered X rows
__device__ float g_Y[(size_t)2 * T_TOK * D_MODEL];
__device__ int   g_alist[N_EXP * T_TOK];
__device__ float g_wlist[N_EXP * T_TOK];
__device__ int   g_count[N_EXP];

// ---------------- helpers ----------------
__device__ __forceinline__ uint32_t smem_u32(const void* p) {
    uint32_t a;
    asm("{ .reg .u64 t; cvta.to.shared.u64 t, %1; cvt.u32.u64 %0, t; }"
        : "=r"(a) : "l"(p));
    return a;
}
__device__ __forceinline__ void cp16(uint32_t dst, const void* src) {
    asm volatile("cp.async.cg.shared.global [%0], [%1], 16;"
                 :: "r"(dst), "l"(src) : "memory");
}
__device__ __forceinline__ uint32_t f2tf32(float f) {
    uint32_t u;
    asm("cvt.rna.tf32.f32 %0, %1;" : "=r"(u) : "f"(f));
    return u;
}
__device__ __forceinline__ void mma8(float* c, const uint32_t* a, const uint32_t* b) {
    asm volatile(
        "mma.sync.aligned.m16n8k8.row.col.f32.tf32.tf32.f32 "
        "{%0,%1,%2,%3},{%4,%5,%6,%7},{%8,%9},{%0,%1,%2,%3};"
        : "+f"(c[0]), "+f"(c[1]), "+f"(c[2]), "+f"(c[3])
        : "r"(a[0]), "r"(a[1]), "r"(a[2]), "r"(a[3]), "r"(b[0]), "r"(b[1]));
}

// ---------------- small kernels ----------------
__global__ void zero_counts_kernel() {
    int i = threadIdx.x;
    if (i < N_EXP) g_count[i] = 0;
}

__global__ void gate_kernel(const float* __restrict__ x,
                            const float* __restrict__ wg,
                            const float* __restrict__ bg) {
    int warp = (blockIdx.x * blockDim.x + threadIdx.x) >> 5;
    int lane = threadIdx.x & 31;
    if (warp >= T_TOK) return;

    const float* xr = x + (size_t)warp * D_MODEL;
    float acc[N_EXP];
#pragma unroll
    for (int e = 0; e < N_EXP; e++) acc[e] = 0.f;
    for (int d = lane; d < D_MODEL; d += 32) {
        float xv = xr[d];
        const float* wr = wg + (size_t)d * N_EXP;
#pragma unroll
        for (int e = 0; e < N_EXP; e++) acc[e] += xv * wr[e];
    }
#pragma unroll
    for (int e = 0; e < N_EXP; e++) {
#pragma unroll
        for (int off = 16; off > 0; off >>= 1)
            acc[e] += __shfl_xor_sync(0xFFFFFFFFu, acc[e], off);
    }
    if (lane == 0) {
        float v[N_EXP];
#pragma unroll
        for (int e = 0; e < N_EXP; e++) v[e] = acc[e] + bg[e];
        int i0 = 0;
#pragma unroll
        for (int e = 1; e < N_EXP; e++) if (v[e] > v[i0]) i0 = e;
        int i1 = (i0 == 0) ? 1 : 0;
#pragma unroll
        for (int e = 0; e < N_EXP; e++)
            if (e != i0 && v[e] > v[i1]) i1 = e;
        float w0 = 1.0f / (1.0f + expf(v[i1] - v[i0]));
        float w1 = 1.0f - w0;
        int p0 = atomicAdd(&g_count[i0], 1);
        g_alist[i0 * T_TOK + p0] = warp * 2 + 0;
        g_wlist[i0 * T_TOK + p0] = w0;
        int p1 = atomicAdd(&g_count[i1], 1);
        g_alist[i1 * T_TOK + p1] = warp * 2 + 1;
        g_wlist[i1 * T_TOK + p1] = w1;
    }
}

__global__ void gather_kernel(const float* __restrict__ x) {
    int pos = blockIdx.x;
    int e = blockIdx.y;
    if (pos >= g_count[e]) return;
    int tok = g_alist[e * T_TOK + pos] >> 1;
    const float4* src = (const float4*)(x + (size_t)tok * D_MODEL);
    float4* dst = (float4*)(g_Xg + ((size_t)e * T_TOK + pos) * D_MODEL);
    dst[threadIdx.x] = src[threadIdx.x];
}

// ---------------- mma.sync tf32 grouped GEMM ----------------
// CTA tile 128x256, BK=32, 8 warps, warp tile 64x64 (2x4 warp grid).
#define BM 128
#define BN 256
#define BK 32
#define A_LD 36                         // padded floats per A row (bank-conflict-free)
#define B_LD 264                        // padded floats per B k-row
#define A_FLOATS (BM * A_LD)            // 4608
#define B_FLOATS (BK * B_LD)            // 8448
#define BUF_FLOATS (A_FLOATS + B_FLOATS)
#define SMEM_DYN (2 * BUF_FLOATS * 4)   // 104448 bytes

// MODE 0: H = relu(Xg @ w1 + b1)   (K=1024, NW=4096)
// MODE 1: Y = wgt * (H @ w2 + b2)  (K=4096, NW=1024)
template <int MODE>
__global__ void __launch_bounds__(256, 1) moe_gemm(const float* __restrict__ W,
                                                   const float* __restrict__ bias) {
    constexpr int K  = MODE ? D_FF : D_MODEL;
    constexpr int NW = MODE ? D_MODEL : D_FF;
    constexpr int NC = K / BK;

    int e = blockIdx.z;
    int cnt = g_count[e];
    int m0 = blockIdx.y * BM;
    if (m0 >= cnt) return;
    int n0 = blockIdx.x * BN;

    const float* A  = (MODE ? g_H : g_Xg) + ((size_t)e * T_TOK + m0) * K;
    const float* Bw = W + (size_t)e * K * NW + n0;

    extern __shared__ __align__(16) float sm_f[];
    uint32_t sb = smem_u32(sm_f);

    int tid = threadIdx.x, lane = tid & 31, wid = tid >> 5;
    int wm = (wid >> 2) * 64;   // warp m offset: 0 or 64
    int wn = (wid & 3) * 64;    // warp n offset: 0..192
    int qrow = lane >> 2;       // 0..7
    int qcol = lane & 3;        // 0..3

    // ---- async tile loaders ----
    // A: 128 rows x 128B = 1024 x cp16 ; idx -> m = idx>>3, kq = idx&7
    // B: 32 k-rows x 1024B = 2048 x cp16 ; idx -> k = idx>>6, n16 = idx&63
    auto load_chunk = [&](int c, int p) {
        uint32_t sA = sb + (uint32_t)p * (BUF_FLOATS * 4);
        uint32_t sB = sA + A_FLOATS * 4;
        int k0 = c * BK;
#pragma unroll
        for (int i = 0; i < 4; i++) {
            int idx = i * 256 + tid;
            int m = idx >> 3, kq = idx & 7;
            cp16(sA + (uint32_t)m * (A_LD * 4) + (uint32_t)kq * 16,
                 A + (size_t)m * K + k0 + kq * 4);
        }
#pragma unroll
        for (int i = 0; i < 8; i++) {
            int idx = i * 256 + tid;
            int k = idx >> 6, n16 = idx & 63;
            cp16(sB + (uint32_t)k * (B_LD * 4) + (uint32_t)n16 * 16,
                 Bw + (size_t)(k0 + k) * NW + n16 * 4);
        }
        asm volatile("cp.async.commit_group;" ::: "memory");
    };

    float acc[4][8][4];
#pragma unroll
    for (int mt = 0; mt < 4; mt++)
#pragma unroll
        for (int nt = 0; nt < 8; nt++)
#pragma unroll
            for (int q = 0; q < 4; q++) acc[mt][nt][q] = 0.f;

    load_chunk(0, 0);
    load_chunk(1, 1);

    for (int c = 0; c < NC; c++) {
        if (c + 1 < NC) asm volatile("cp.async.wait_group 1;" ::: "memory");
        else            asm volatile("cp.async.wait_group 0;" ::: "memory");
        __syncthreads();

        int p = c & 1;
        const float* As = sm_f + (size_t)p * BUF_FLOATS;
        const float* Bs = As + A_FLOATS;

#pragma unroll
        for (int s = 0; s < 4; s++) {
            int kq = s * 8 + qcol;
            uint32_t af[4][4];
#pragma unroll
            for (int mt = 0; mt < 4; mt++) {
                int r = wm + mt * 16 + qrow;
                af[mt][0] = f2tf32(As[r * A_LD + kq]);
                af[mt][1] = f2tf32(As[(r + 8) * A_LD + kq]);
                af[mt][2] = f2tf32(As[r * A_LD + kq + 4]);
                af[mt][3] = f2tf32(As[(r + 8) * A_LD + kq + 4]);
            }
            uint32_t bf[8][2];
#pragma unroll
            for (int nt = 0; nt < 8; nt++) {
                int cn = wn + nt * 8 + qrow;
                bf[nt][0] = f2tf32(Bs[kq * B_LD + cn]);
                bf[nt][1] = f2tf32(Bs[(kq + 4) * B_LD + cn]);
            }
#pragma unroll
            for (int mt = 0; mt < 4; mt++)
#pragma unroll
                for (int nt = 0; nt < 8; nt++)
                    mma8(acc[mt][nt], af[mt], bf[nt]);
        }
        __syncthreads();
        if (c + 2 < NC) load_chunk(c + 2, p);
    }

    // ---- epilogue ----
    const float* be = bias + (size_t)e * NW;
#pragma unroll
    for (int mt = 0; mt < 4; mt++) {
        int r0 = m0 + wm + mt * 16 + qrow;
        int r1 = r0 + 8;
        bool v0 = r0 < cnt, v1 = r1 < cnt;
        int aid0 = 0, aid1 = 0;
        float wg0 = 0.f, wg1 = 0.f;
        if (MODE == 1) {
            if (v0) { aid0 = g_alist[e * T_TOK + r0]; wg0 = g_wlist[e * T_TOK + r0]; }
            if (v1) { aid1 = g_alist[e * T_TOK + r1]; wg1 = g_wlist[e * T_TOK + r1]; }
        }
#pragma unroll
        for (int nt = 0; nt < 8; nt++) {
            int n = n0 + wn + nt * 8 + 2 * qcol;
            float2 b2 = *(const float2*)(be + n);
            float* cc = acc[mt][nt];
            if (v0) {
                float x0 = cc[0] + b2.x, x1 = cc[1] + b2.y;
                float2 o;
                if (MODE == 0) {
                    o.x = x0 > 0.f ? x0 : 0.f;
                    o.y = x1 > 0.f ? x1 : 0.f;
                    *(float2*)(g_H + ((size_t)e * T_TOK + r0) * D_FF + n) = o;
                } else {
                    o.x = x0 * wg0; o.y = x1 * wg0;
                    *(float2*)(g_Y + (size_t)aid0 * D_MODEL + n) = o;
                }
            }
            if (v1) {
                float x2 = cc[2] + b2.x, x3 = cc[3] + b2.y;
                float2 o;
                if (MODE == 0) {
                    o.x = x2 > 0.f ? x2 : 0.f;
                    o.y = x3 > 0.f ? x3 : 0.f;
                    *(float2*)(g_H + ((size_t)e * T_TOK + r1) * D_FF + n) = o;
                } else {
                    o.x = x2 * wg1; o.y = x3 * wg1;
                    *(float2*)(g_Y + (size_t)aid1 * D_MODEL + n) = o;
                }
            }
        }
    }
}

// ---------------- combine: out[t] = Y[2t] + Y[2t+1] ----------------
__global__ void combine_kernel(float* __restrict__ out) {
    int i = blockIdx.x * blockDim.x + threadIdx.x;
    int total = T_TOK * D_MODEL / 4;
    if (i >= total) return;
    int t = (i * 4) >> 10;
    const float4* y0 = (const float4*)(g_Y + (size_t)(2 * t) * D_MODEL) + (i & 255);
    const float4* y1 = (const float4*)(g_Y + (size_t)(2 * t + 1) * D_MODEL) + (i & 255);
    float4 a = *y0, b = *y1;
    float4 r;
    r.x = a.x + b.x; r.y = a.y + b.y; r.z = a.z + b.z; r.w = a.w + b.w;
    ((float4*)out)[i] = r;
}

// ---------------- launch ----------------
extern "C" void kernel_launch(void* const* d_in, const int* in_sizes, int n_in,
                              void* d_out, int out_size) {
    const float* x   = (const float*)d_in[0];
    const float* wg  = (const float*)d_in[1];
    const float* bg  = (const float*)d_in[2];
    const float* w1  = (const float*)d_in[3];
    const float* b1  = (const float*)d_in[4];
    const float* w2  = (const float*)d_in[5];
    const float* b2  = (const float*)d_in[6];
    float* out = (float*)d_out;

    cudaFuncSetAttribute(moe_gemm<0>, cudaFuncAttributeMaxDynamicSharedMemorySize, SMEM_DYN);
    cudaFuncSetAttribute(moe_gemm<1>, cudaFuncAttributeMaxDynamicSharedMemorySize, SMEM_DYN);

    zero_counts_kernel<<<1, 32>>>();
    gate_kernel<<<(T_TOK * 32) / 256, 256>>>(x, wg, bg);

    dim3 gg(T_TOK, N_EXP);
    gather_kernel<<<gg, 256>>>(x);

    dim3 g1(D_FF / BN, T_TOK / BM, N_EXP);     // 16 x 16 x 8
    moe_gemm<0><<<g1, 256, SMEM_DYN>>>(w1, b1);

    dim3 g2(D_MODEL / BN, T_TOK / BM, N_EXP);  // 4 x 16 x 8
    moe_gemm<1><<<g2, 256, SMEM_DYN>>>(w2, b2);

    combine_kernel<<<(T_TOK * D_MODEL / 4 + 255) / 256, 256>>>(out);
}

// round 7
// speedup vs baseline: 3.6067x; 1.0189x over previous
#include <cuda_runtime.h>
#include <math.h>
#include <stdint.h>

#define T_TOK 2048
#define D_MODEL 1024
#define D_FF 4096
#define N_EXP 8

// ---------------- static scratch (no allocations allowed) ----------------
__device__ float g_H[(size_t)N_EXP * T_TOK * D_FF];      // row-major [e][pos][ff]
__device__ float g_Xg[(size_t)N_EXP * T_TOK * D_MODEL];  // gathered X rows
__device__ float g_Y[(size_t)2 * T_TOK * D_MODEL];
__device__ int   g_alist[N_EXP * T_TOK];
__device__ float g_wlist[N_EXP * T_TOK];
__device__ int   g_count[N_EXP];

// ---------------- helpers ----------------
__device__ __forceinline__ uint32_t smem_u32(const void* p) {
    uint32_t a;
    asm("{ .reg .u64 t; cvta.to.shared.u64 t, %1; cvt.u32.u64 %0, t; }"
        : "=r"(a) : "l"(p));
    return a;
}
__device__ __forceinline__ void cp16(uint32_t dst, const void* src) {
    asm volatile("cp.async.cg.shared.global [%0], [%1], 16;"
                 :: "r"(dst), "l"(src) : "memory");
}
__device__ __forceinline__ uint32_t f2tf32(float f) {
    uint32_t u;
    asm("cvt.rna.tf32.f32 %0, %1;" : "=r"(u) : "f"(f));
    return u;
}
__device__ __forceinline__ void mma8(float* c, const uint32_t* a, const uint32_t* b) {
    asm volatile(
        "mma.sync.aligned.m16n8k8.row.col.f32.tf32.tf32.f32 "
        "{%0,%1,%2,%3},{%4,%5,%6,%7},{%8,%9},{%0,%1,%2,%3};"
        : "+f"(c[0]), "+f"(c[1]), "+f"(c[2]), "+f"(c[3])
        : "r"(a[0]), "r"(a[1]), "r"(a[2]), "r"(a[3]), "r"(b[0]), "r"(b[1]));
}

// ---------------- small kernels ----------------
__global__ void zero_counts_kernel() {
    int i = threadIdx.x;
    if (i < N_EXP) g_count[i] = 0;
}

__global__ void gate_kernel(const float* __restrict__ x,
                            const float* __restrict__ wg,
                            const float* __restrict__ bg) {
    int warp = (blockIdx.x * blockDim.x + threadIdx.x) >> 5;
    int lane = threadIdx.x & 31;
    if (warp >= T_TOK) return;

    const float* xr = x + (size_t)warp * D_MODEL;
    float acc[N_EXP];
#pragma unroll
    for (int e = 0; e < N_EXP; e++) acc[e] = 0.f;
    for (int d = lane; d < D_MODEL; d += 32) {
        float xv = xr[d];
        const float* wr = wg + (size_t)d * N_EXP;
#pragma unroll
        for (int e = 0; e < N_EXP; e++) acc[e] += xv * wr[e];
    }
#pragma unroll
    for (int e = 0; e < N_EXP; e++) {
#pragma unroll
        for (int off = 16; off > 0; off >>= 1)
            acc[e] += __shfl_xor_sync(0xFFFFFFFFu, acc[e], off);
    }
    if (lane == 0) {
        float v[N_EXP];
#pragma unroll
        for (int e = 0; e < N_EXP; e++) v[e] = acc[e] + bg[e];
        int i0 = 0;
#pragma unroll
        for (int e = 1; e < N_EXP; e++) if (v[e] > v[i0]) i0 = e;
        int i1 = (i0 == 0) ? 1 : 0;
#pragma unroll
        for (int e = 0; e < N_EXP; e++)
            if (e != i0 && v[e] > v[i1]) i1 = e;
        float w0 = 1.0f / (1.0f + expf(v[i1] - v[i0]));
        float w1 = 1.0f - w0;
        int p0 = atomicAdd(&g_count[i0], 1);
        g_alist[i0 * T_TOK + p0] = warp * 2 + 0;
        g_wlist[i0 * T_TOK + p0] = w0;
        int p1 = atomicAdd(&g_count[i1], 1);
        g_alist[i1 * T_TOK + p1] = warp * 2 + 1;
        g_wlist[i1 * T_TOK + p1] = w1;
    }
}

__global__ void gather_kernel(const float* __restrict__ x) {
    int pos = blockIdx.x;
    int e = blockIdx.y;
    if (pos >= g_count[e]) return;
    int tok = g_alist[e * T_TOK + pos] >> 1;
    const float4* src = (const float4*)(x + (size_t)tok * D_MODEL);
    float4* dst = (float4*)(g_Xg + ((size_t)e * T_TOK + pos) * D_MODEL);
    dst[threadIdx.x] = src[threadIdx.x];
}

// ---------------- mma.sync tf32 grouped GEMM ----------------
// CTA tile 128x256, BK=32, 8 warps, warp tile 64x64 (2x4 warp grid).
// 3-stage cp.async pipeline + register-level fragment double buffering.
#define BM 128
#define BN 256
#define BK 32
#define STAGES 3
#define A_LD 36
#define B_LD 264
#define A_FLOATS (BM * A_LD)            // 4608
#define B_FLOATS (BK * B_LD)            // 8448
#define BUF_FLOATS (A_FLOATS + B_FLOATS)
#define SMEM_DYN (STAGES * BUF_FLOATS * 4)   // 156672 bytes

// MODE 0: H = relu(Xg @ w1 + b1)   (K=1024, NW=4096)
// MODE 1: Y = wgt * (H @ w2 + b2)  (K=4096, NW=1024)
template <int MODE>
__global__ void __launch_bounds__(256, 1) moe_gemm(const float* __restrict__ W,
                                                   const float* __restrict__ bias) {
    constexpr int K  = MODE ? D_FF : D_MODEL;
    constexpr int NW = MODE ? D_MODEL : D_FF;
    constexpr int NC = K / BK;

    int e = blockIdx.z;
    int cnt = g_count[e];
    int m0 = blockIdx.y * BM;
    if (m0 >= cnt) return;
    int n0 = blockIdx.x * BN;

    const float* A  = (MODE ? g_H : g_Xg) + ((size_t)e * T_TOK + m0) * K;
    const float* Bw = W + (size_t)e * K * NW + n0;

    extern __shared__ __align__(16) float sm_f[];
    uint32_t sb = smem_u32(sm_f);

    int tid = threadIdx.x, lane = tid & 31, wid = tid >> 5;
    int wm = (wid >> 2) * 64;
    int wn = (wid & 3) * 64;
    int qrow = lane >> 2;
    int qcol = lane & 3;

    auto load_chunk = [&](int c, int p) {
        uint32_t sA = sb + (uint32_t)p * (BUF_FLOATS * 4);
        uint32_t sB = sA + A_FLOATS * 4;
        int k0 = c * BK;
#pragma unroll
        for (int i = 0; i < 4; i++) {
            int idx = i * 256 + tid;
            int m = idx >> 3, kq = idx & 7;
            cp16(sA + (uint32_t)m * (A_LD * 4) + (uint32_t)kq * 16,
                 A + (size_t)m * K + k0 + kq * 4);
        }
#pragma unroll
        for (int i = 0; i < 8; i++) {
            int idx = i * 256 + tid;
            int k = idx >> 6, n16 = idx & 63;
            cp16(sB + (uint32_t)k * (B_LD * 4) + (uint32_t)n16 * 16,
                 Bw + (size_t)(k0 + k) * NW + n16 * 4);
        }
        asm volatile("cp.async.commit_group;" ::: "memory");
    };

    float acc[4][8][4];
#pragma unroll
    for (int mt = 0; mt < 4; mt++)
#pragma unroll
        for (int nt = 0; nt < 8; nt++)
#pragma unroll
            for (int q = 0; q < 4; q++) acc[mt][nt][q] = 0.f;

    load_chunk(0, 0);
    load_chunk(1, 1);
    load_chunk(2, 2);

    uint32_t af[2][4][4];
    uint32_t bf[2][8][2];

    // fragment loader for k-step s of the chunk resident in (As, Bs)
    auto load_frags = [&](const float* As, const float* Bs, int s, int slot) {
        int kq = s * 8 + qcol;
#pragma unroll
        for (int mt = 0; mt < 4; mt++) {
            int r = wm + mt * 16 + qrow;
            af[slot][mt][0] = f2tf32(As[r * A_LD + kq]);
            af[slot][mt][1] = f2tf32(As[(r + 8) * A_LD + kq]);
            af[slot][mt][2] = f2tf32(As[r * A_LD + kq + 4]);
            af[slot][mt][3] = f2tf32(As[(r + 8) * A_LD + kq + 4]);
        }
#pragma unroll
        for (int nt = 0; nt < 8; nt++) {
            int cn = wn + nt * 8 + qrow;
            bf[slot][nt][0] = f2tf32(Bs[kq * B_LD + cn]);
            bf[slot][nt][1] = f2tf32(Bs[(kq + 4) * B_LD + cn]);
        }
    };

    for (int c = 0; c < NC; c++) {
        int rem = NC - c;
        if (rem > 2)       asm volatile("cp.async.wait_group 2;" ::: "memory");
        else if (rem == 2) asm volatile("cp.async.wait_group 1;" ::: "memory");
        else               asm volatile("cp.async.wait_group 0;" ::: "memory");
        __syncthreads();

        int p = c % STAGES;
        const float* As = sm_f + (size_t)p * BUF_FLOATS;
        const float* Bs = As + A_FLOATS;

        load_frags(As, Bs, 0, 0);
#pragma unroll
        for (int s = 0; s < 4; s++) {
            int cur = s & 1;
            if (s < 3) load_frags(As, Bs, s + 1, cur ^ 1);
#pragma unroll
            for (int mt = 0; mt < 4; mt++)
#pragma unroll
                for (int nt = 0; nt < 8; nt++)
                    mma8(acc[mt][nt], af[cur][mt], bf[cur][nt]);
        }
        __syncthreads();
        if (c + STAGES < NC) load_chunk(c + STAGES, p);
    }

    // ---- epilogue ----
    const float* be = bias + (size_t)e * NW;
#pragma unroll
    for (int mt = 0; mt < 4; mt++) {
        int r0 = m0 + wm + mt * 16 + qrow;
        int r1 = r0 + 8;
        bool v0 = r0 < cnt, v1 = r1 < cnt;
        int aid0 = 0, aid1 = 0;
        float wg0 = 0.f, wg1 = 0.f;
        if (MODE == 1) {
            if (v0) { aid0 = g_alist[e * T_TOK + r0]; wg0 = g_wlist[e * T_TOK + r0]; }
            if (v1) { aid1 = g_alist[e * T_TOK + r1]; wg1 = g_wlist[e * T_TOK + r1]; }
        }
#pragma unroll
        for (int nt = 0; nt < 8; nt++) {
            int n = n0 + wn + nt * 8 + 2 * qcol;
            float2 b2 = *(const float2*)(be + n);
            float* cc = acc[mt][nt];
            if (v0) {
                float x0 = cc[0] + b2.x, x1 = cc[1] + b2.y;
                float2 o;
                if (MODE == 0) {
                    o.x = x0 > 0.f ? x0 : 0.f;
                    o.y = x1 > 0.f ? x1 : 0.f;
                    *(float2*)(g_H + ((size_t)e * T_TOK + r0) * D_FF + n) = o;
                } else {
                    o.x = x0 * wg0; o.y = x1 * wg0;
                    *(float2*)(g_Y + (size_t)aid0 * D_MODEL + n) = o;
                }
            }
            if (v1) {
                float x2 = cc[2] + b2.x, x3 = cc[3] + b2.y;
                float2 o;
                if (MODE == 0) {
                    o.x = x2 > 0.f ? x2 : 0.f;
                    o.y = x3 > 0.f ? x3 : 0.f;
                    *(float2*)(g_H + ((size_t)e * T_TOK + r1) * D_FF + n) = o;
                } else {
                    o.x = x2 * wg1; o.y = x3 * wg1;
                    *(float2*)(g_Y + (size_t)aid1 * D_MODEL + n) = o;
                }
            }
        }
    }
}

// ---------------- combine: out[t] = Y[2t] + Y[2t+1] ----------------
__global__ void combine_kernel(float* __restrict__ out) {
    int i = blockIdx.x * blockDim.x + threadIdx.x;
    int total = T_TOK * D_MODEL / 4;
    if (i >= total) return;
    int t = (i * 4) >> 10;
    const float4* y0 = (const float4*)(g_Y + (size_t)(2 * t) * D_MODEL) + (i & 255);
    const float4* y1 = (const float4*)(g_Y + (size_t)(2 * t + 1) * D_MODEL) + (i & 255);
    float4 a = *y0, b = *y1;
    float4 r;
    r.x = a.x + b.x; r.y = a.y + b.y; r.z = a.z + b.z; r.w = a.w + b.w;
    ((float4*)out)[i] = r;
}

// ---------------- launch ----------------
extern "C" void kernel_launch(void* const* d_in, const int* in_sizes, int n_in,
                              void* d_out, int out_size) {
    const float* x   = (const float*)d_in[0];
    const float* wg  = (const float*)d_in[1];
    const float* bg  = (const float*)d_in[2];
    const float* w1  = (const float*)d_in[3];
    const float* b1  = (const float*)d_in[4];
    const float* w2  = (const float*)d_in[5];
    const float* b2  = (const float*)d_in[6];
    float* out = (float*)d_out;

    cudaFuncSetAttribute(moe_gemm<0>, cudaFuncAttributeMaxDynamicSharedMemorySize, SMEM_DYN);
    cudaFuncSetAttribute(moe_gemm<1>, cudaFuncAttributeMaxDynamicSharedMemorySize, SMEM_DYN);

    zero_counts_kernel<<<1, 32>>>();
    gate_kernel<<<(T_TOK * 32) / 256, 256>>>(x, wg, bg);

    dim3 gg(T_TOK, N_EXP);
    gather_kernel<<<gg, 256>>>(x);

    dim3 g1(D_FF / BN, T_TOK / BM, N_EXP);     // 16 x 16 x 8
    moe_gemm<0><<<g1, 256, SMEM_DYN>>>(w1, b1);

    dim3 g2(D_MODEL / BN, T_TOK / BM, N_EXP);  // 4 x 16 x 8
    moe_gemm<1><<<g2, 256, SMEM_DYN>>>(w2, b2);

    combine_kernel<<<(T_TOK * D_MODEL / 4 + 255) / 256, 256>>>(out);
}

// round 8
// speedup vs baseline: 3.6907x; 1.0233x over previous
#include <cuda_runtime.h>
#include <math.h>
#include <stdint.h>

#define T_TOK 2048
#define D_MODEL 1024
#define D_FF 4096
#define N_EXP 8

// ---------------- static scratch (no allocations allowed) ----------------
__device__ float g_H[(size_t)N_EXP * T_TOK * D_FF];      // row-major [e][pos][ff], tf32-rounded
__device__ float g_Xg[(size_t)N_EXP * T_TOK * D_MODEL];  // gathered X rows, tf32-rounded
__device__ float g_Y[(size_t)2 * T_TOK * D_MODEL];
__device__ int   g_alist[N_EXP * T_TOK];
__device__ float g_wlist[N_EXP * T_TOK];
__device__ int   g_count[N_EXP];

// ---------------- helpers ----------------
__device__ __forceinline__ void cp16(uint32_t dst, const void* src) {
    asm volatile("cp.async.cg.shared.global [%0], [%1], 16;"
                 :: "r"(dst), "l"(src) : "memory");
}
__device__ __forceinline__ uint32_t smem_u32(const void* p) {
    uint32_t a;
    asm("{ .reg .u64 t; cvta.to.shared.u64 t, %1; cvt.u32.u64 %0, t; }"
        : "=r"(a) : "l"(p));
    return a;
}
__device__ __forceinline__ uint32_t f2tf32(float f) {
    uint32_t u;
    asm("cvt.rna.tf32.f32 %0, %1;" : "=r"(u) : "f"(f));
    return u;
}
__device__ __forceinline__ float f2tf32f(float f) {
    uint32_t u = f2tf32(f);
    return __uint_as_float(u);
}
__device__ __forceinline__ void mma8(float* c, const uint32_t* a, const uint32_t* b) {
    asm volatile(
        "mma.sync.aligned.m16n8k8.row.col.f32.tf32.tf32.f32 "
        "{%0,%1,%2,%3},{%4,%5,%6,%7},{%8,%9},{%0,%1,%2,%3};"
        : "+f"(c[0]), "+f"(c[1]), "+f"(c[2]), "+f"(c[3])
        : "r"(a[0]), "r"(a[1]), "r"(a[2]), "r"(a[3]), "r"(b[0]), "r"(b[1]));
}

// ---------------- small kernels ----------------
__global__ void zero_counts_kernel() {
    int i = threadIdx.x;
    if (i < N_EXP) g_count[i] = 0;
}

__global__ void gate_kernel(const float* __restrict__ x,
                            const float* __restrict__ wg,
                            const float* __restrict__ bg) {
    int warp = (blockIdx.x * blockDim.x + threadIdx.x) >> 5;
    int lane = threadIdx.x & 31;
    if (warp >= T_TOK) return;

    const float* xr = x + (size_t)warp * D_MODEL;
    float acc[N_EXP];
#pragma unroll
    for (int e = 0; e < N_EXP; e++) acc[e] = 0.f;
    for (int d = lane; d < D_MODEL; d += 32) {
        float xv = xr[d];
        const float* wr = wg + (size_t)d * N_EXP;
#pragma unroll
        for (int e = 0; e < N_EXP; e++) acc[e] += xv * wr[e];
    }
#pragma unroll
    for (int e = 0; e < N_EXP; e++) {
#pragma unroll
        for (int off = 16; off > 0; off >>= 1)
            acc[e] += __shfl_xor_sync(0xFFFFFFFFu, acc[e], off);
    }
    if (lane == 0) {
        float v[N_EXP];
#pragma unroll
        for (int e = 0; e < N_EXP; e++) v[e] = acc[e] + bg[e];
        int i0 = 0;
#pragma unroll
        for (int e = 1; e < N_EXP; e++) if (v[e] > v[i0]) i0 = e;
        int i1 = (i0 == 0) ? 1 : 0;
#pragma unroll
        for (int e = 0; e < N_EXP; e++)
            if (e != i0 && v[e] > v[i1]) i1 = e;
        float w0 = 1.0f / (1.0f + expf(v[i1] - v[i0]));
        float w1 = 1.0f - w0;
        int p0 = atomicAdd(&g_count[i0], 1);
        g_alist[i0 * T_TOK + p0] = warp * 2 + 0;
        g_wlist[i0 * T_TOK + p0] = w0;
        int p1 = atomicAdd(&g_count[i1], 1);
        g_alist[i1 * T_TOK + p1] = warp * 2 + 1;
        g_wlist[i1 * T_TOK + p1] = w1;
    }
}

// gather + pre-round to tf32 (A-side of GEMM1 needs no mainloop CVT)
__global__ void gather_kernel(const float* __restrict__ x) {
    int pos = blockIdx.x;
    int e = blockIdx.y;
    if (pos >= g_count[e]) return;
    int tok = g_alist[e * T_TOK + pos] >> 1;
    const float4* src = (const float4*)(x + (size_t)tok * D_MODEL);
    float4* dst = (float4*)(g_Xg + ((size_t)e * T_TOK + pos) * D_MODEL);
    float4 v = src[threadIdx.x];
    v.x = f2tf32f(v.x); v.y = f2tf32f(v.y);
    v.z = f2tf32f(v.z); v.w = f2tf32f(v.w);
    dst[threadIdx.x] = v;
}

// ---------------- mma.sync tf32 grouped GEMM ----------------
// CTA tile 128x128, BK=32, 8 warps, warp tile 32x64 (4x2 warp grid).
// 3-stage cp.async pipeline; 2 CTAs/SM (4 warps/SMSP).
#define BM 128
#define BN 128
#define BK 32
#define STAGES 3
#define A_LD 36
#define B_LD 136
#define A_FLOATS (BM * A_LD)            // 4608
#define B_FLOATS (BK * B_LD)            // 4352
#define BUF_FLOATS (A_FLOATS + B_FLOATS)
#define SMEM_DYN (STAGES * BUF_FLOATS * 4)   // 107520 bytes

// MODE 0: H = tf32(relu(Xg @ w1 + b1))   (K=1024, NW=4096)
// MODE 1: Y = wgt * (H @ w2 + b2)        (K=4096, NW=1024)
template <int MODE>
__global__ void __launch_bounds__(256, 2) moe_gemm(const float* __restrict__ W,
                                                   const float* __restrict__ bias) {
    constexpr int K  = MODE ? D_FF : D_MODEL;
    constexpr int NW = MODE ? D_MODEL : D_FF;
    constexpr int NC = K / BK;

    int e = blockIdx.z;
    int cnt = g_count[e];
    int m0 = blockIdx.y * BM;
    if (m0 >= cnt) return;
    int n0 = blockIdx.x * BN;

    const float* A  = (MODE ? g_H : g_Xg) + ((size_t)e * T_TOK + m0) * K;
    const float* Bw = W + (size_t)e * K * NW + n0;

    extern __shared__ __align__(16) float sm_f[];
    uint32_t sb = smem_u32(sm_f);

    int tid = threadIdx.x, lane = tid & 31, wid = tid >> 5;
    int wm = (wid >> 1) * 32;   // warp m offset: 0,32,64,96
    int wn = (wid & 1) * 64;    // warp n offset: 0,64
    int qrow = lane >> 2;
    int qcol = lane & 3;

    // A: 128 rows x 128B = 1024 16B-units; B: 32 rows x 512B = 1024 units
    auto load_chunk = [&](int c, int p) {
        uint32_t sA = sb + (uint32_t)p * (BUF_FLOATS * 4);
        uint32_t sB = sA + A_FLOATS * 4;
        int k0 = c * BK;
#pragma unroll
        for (int i = 0; i < 4; i++) {
            int idx = i * 256 + tid;
            int m = idx >> 3, kq = idx & 7;
            cp16(sA + (uint32_t)m * (A_LD * 4) + (uint32_t)kq * 16,
                 A + (size_t)m * K + k0 + kq * 4);
        }
#pragma unroll
        for (int i = 0; i < 4; i++) {
            int idx = i * 256 + tid;
            int k = idx >> 5, n16 = idx & 31;
            cp16(sB + (uint32_t)k * (B_LD * 4) + (uint32_t)n16 * 16,
                 Bw + (size_t)(k0 + k) * NW + n16 * 4);
        }
        asm volatile("cp.async.commit_group;" ::: "memory");
    };

    float acc[2][8][4];
#pragma unroll
    for (int mt = 0; mt < 2; mt++)
#pragma unroll
        for (int nt = 0; nt < 8; nt++)
#pragma unroll
            for (int q = 0; q < 4; q++) acc[mt][nt][q] = 0.f;

    load_chunk(0, 0);
    load_chunk(1, 1);
    load_chunk(2, 2);

    for (int c = 0; c < NC; c++) {
        int rem = NC - c;
        if (rem > 2)       asm volatile("cp.async.wait_group 2;" ::: "memory");
        else if (rem == 2) asm volatile("cp.async.wait_group 1;" ::: "memory");
        else               asm volatile("cp.async.wait_group 0;" ::: "memory");
        __syncthreads();

        int p = c % STAGES;
        const float* As = sm_f + (size_t)p * BUF_FLOATS;
        const float* Bs = As + A_FLOATS;

#pragma unroll
        for (int s = 0; s < 4; s++) {
            int kq = s * 8 + qcol;
            uint32_t af[2][4];
#pragma unroll
            for (int mt = 0; mt < 2; mt++) {
                int r = wm + mt * 16 + qrow;
                af[mt][0] = __float_as_uint(As[r * A_LD + kq]);          // pre-rounded
                af[mt][1] = __float_as_uint(As[(r + 8) * A_LD + kq]);
                af[mt][2] = __float_as_uint(As[r * A_LD + kq + 4]);
                af[mt][3] = __float_as_uint(As[(r + 8) * A_LD + kq + 4]);
            }
            uint32_t bf[8][2];
#pragma unroll
            for (int nt = 0; nt < 8; nt++) {
                int cn = wn + nt * 8 + qrow;
                bf[nt][0] = f2tf32(Bs[kq * B_LD + cn]);
                bf[nt][1] = f2tf32(Bs[(kq + 4) * B_LD + cn]);
            }
#pragma unroll
            for (int mt = 0; mt < 2; mt++)
#pragma unroll
                for (int nt = 0; nt < 8; nt++)
                    mma8(acc[mt][nt], af[mt], bf[nt]);
        }
        __syncthreads();
        if (c + STAGES < NC) load_chunk(c + STAGES, p);
    }

    // ---- epilogue ----
    const float* be = bias + (size_t)e * NW;
#pragma unroll
    for (int mt = 0; mt < 2; mt++) {
        int r0 = m0 + wm + mt * 16 + qrow;
        int r1 = r0 + 8;
        bool v0 = r0 < cnt, v1 = r1 < cnt;
        int aid0 = 0, aid1 = 0;
        float wg0 = 0.f, wg1 = 0.f;
        if (MODE == 1) {
            if (v0) { aid0 = g_alist[e * T_TOK + r0]; wg0 = g_wlist[e * T_TOK + r0]; }
            if (v1) { aid1 = g_alist[e * T_TOK + r1]; wg1 = g_wlist[e * T_TOK + r1]; }
        }
#pragma unroll
        for (int nt = 0; nt < 8; nt++) {
            int n = n0 + wn + nt * 8 + 2 * qcol;
            float2 b2 = *(const float2*)(be + n);
            float* cc = acc[mt][nt];
            if (v0) {
                float x0 = cc[0] + b2.x, x1 = cc[1] + b2.y;
                float2 o;
                if (MODE == 0) {
                    o.x = f2tf32f(x0 > 0.f ? x0 : 0.f);   // pre-round H for GEMM2 A-side
                    o.y = f2tf32f(x1 > 0.f ? x1 : 0.f);
                    *(float2*)(g_H + ((size_t)e * T_TOK + r0) * D_FF + n) = o;
                } else {
                    o.x = x0 * wg0; o.y = x1 * wg0;
                    *(float2*)(g_Y + (size_t)aid0 * D_MODEL + n) = o;
                }
            }
            if (v1) {
                float x2 = cc[2] + b2.x, x3 = cc[3] + b2.y;
                float2 o;
                if (MODE == 0) {
                    o.x = f2tf32f(x2 > 0.f ? x2 : 0.f);
                    o.y = f2tf32f(x3 > 0.f ? x3 : 0.f);
                    *(float2*)(g_H + ((size_t)e * T_TOK + r1) * D_FF + n) = o;
                } else {
                    o.x = x2 * wg1; o.y = x3 * wg1;
                    *(float2*)(g_Y + (size_t)aid1 * D_MODEL + n) = o;
                }
            }
        }
    }
}

// ---------------- combine: out[t] = Y[2t] + Y[2t+1] ----------------
__global__ void combine_kernel(float* __restrict__ out) {
    int i = blockIdx.x * blockDim.x + threadIdx.x;
    int total = T_TOK * D_MODEL / 4;
    if (i >= total) return;
    int t = (i * 4) >> 10;
    const float4* y0 = (const float4*)(g_Y + (size_t)(2 * t) * D_MODEL) + (i & 255);
    const float4* y1 = (const float4*)(g_Y + (size_t)(2 * t + 1) * D_MODEL) + (i & 255);
    float4 a = *y0, b = *y1;
    float4 r;
    r.x = a.x + b.x; r.y = a.y + b.y; r.z = a.z + b.z; r.w = a.w + b.w;
    ((float4*)out)[i] = r;
}

// ---------------- launch ----------------
extern "C" void kernel_launch(void* const* d_in, const int* in_sizes, int n_in,
                              void* d_out, int out_size) {
    const float* x   = (const float*)d_in[0];
    const float* wg  = (const float*)d_in[1];
    const float* bg  = (const float*)d_in[2];
    const float* w1  = (const float*)d_in[3];
    const float* b1  = (const float*)d_in[4];
    const float* w2  = (const float*)d_in[5];
    const float* b2  = (const float*)d_in[6];
    float* out = (float*)d_out;

    cudaFuncSetAttribute(moe_gemm<0>, cudaFuncAttributeMaxDynamicSharedMemorySize, SMEM_DYN);
    cudaFuncSetAttribute(moe_gemm<1>, cudaFuncAttributeMaxDynamicSharedMemorySize, SMEM_DYN);

    zero_counts_kernel<<<1, 32>>>();
    gate_kernel<<<(T_TOK * 32) / 256, 256>>>(x, wg, bg);

    dim3 gg(T_TOK, N_EXP);
    gather_kernel<<<gg, 256>>>(x);

    dim3 g1(D_FF / BN, T_TOK / BM, N_EXP);     // 32 x 16 x 8
    moe_gemm<0><<<g1, 256, SMEM_DYN>>>(w1, b1);

    dim3 g2(D_MODEL / BN, T_TOK / BM, N_EXP);  // 8 x 16 x 8
    moe_gemm<1><<<g2, 256, SMEM_DYN>>>(w2, b2);

    combine_kernel<<<(T_TOK * D_MODEL / 4 + 255) / 256, 256>>>(out);
}

// round 10
// speedup vs baseline: 3.9341x; 1.0660x over previous
#include <cuda_runtime.h>
#include <math.h>
#include <stdint.h>

#define T_TOK 2048
#define D_MODEL 1024
#define D_FF 4096
#define N_EXP 8

// ---------------- static scratch (no allocations allowed) ----------------
__device__ float g_H[(size_t)N_EXP * T_TOK * D_FF];      // row-major [e][pos][ff], tf32-rounded
__device__ float g_Xg[(size_t)N_EXP * T_TOK * D_MODEL];  // gathered X rows, tf32-rounded
__device__ float g_Y[(size_t)2 * T_TOK * D_MODEL];
__device__ int   g_alist[N_EXP * T_TOK];
__device__ float g_wlist[N_EXP * T_TOK];
__device__ int   g_count[N_EXP];

// ---------------- helpers ----------------
__device__ __forceinline__ void cp16(uint32_t dst, const void* src) {
    asm volatile("cp.async.cg.shared.global [%0], [%1], 16;"
                 :: "r"(dst), "l"(src) : "memory");
}
__device__ __forceinline__ uint32_t smem_u32(const void* p) {
    uint32_t a;
    asm("{ .reg .u64 t; cvta.to.shared.u64 t, %1; cvt.u32.u64 %0, t; }"
        : "=r"(a) : "l"(p));
    return a;
}
__device__ __forceinline__ uint32_t f2tf32(float f) {
    uint32_t u;
    asm("cvt.rna.tf32.f32 %0, %1;" : "=r"(u) : "f"(f));
    return u;
}
__device__ __forceinline__ float f2tf32f(float f) {
    uint32_t u = f2tf32(f);
    return __uint_as_float(u);
}
__device__ __forceinline__ void mma8(float* c, const uint32_t* a, const uint32_t* b) {
    asm volatile(
        "mma.sync.aligned.m16n8k8.row.col.f32.tf32.tf32.f32 "
        "{%0,%1,%2,%3},{%4,%5,%6,%7},{%8,%9},{%0,%1,%2,%3};"
        : "+f"(c[0]), "+f"(c[1]), "+f"(c[2]), "+f"(c[3])
        : "r"(a[0]), "r"(a[1]), "r"(a[2]), "r"(a[3]), "r"(b[0]), "r"(b[1]));
}

// ---------------- small kernels ----------------
__global__ void zero_counts_kernel() {
    int i = threadIdx.x;
    if (i < N_EXP) g_count[i] = 0;
}

__global__ void gate_kernel(const float* __restrict__ x,
                            const float* __restrict__ wg,
                            const float* __restrict__ bg) {
    int warp = (blockIdx.x * blockDim.x + threadIdx.x) >> 5;
    int lane = threadIdx.x & 31;
    if (warp >= T_TOK) return;

    const float* xr = x + (size_t)warp * D_MODEL;
    float acc[N_EXP];
#pragma unroll
    for (int e = 0; e < N_EXP; e++) acc[e] = 0.f;
    for (int d = lane; d < D_MODEL; d += 32) {
        float xv = xr[d];
        const float* wr = wg + (size_t)d * N_EXP;
#pragma unroll
        for (int e = 0; e < N_EXP; e++) acc[e] += xv * wr[e];
    }
#pragma unroll
    for (int e = 0; e < N_EXP; e++) {
#pragma unroll
        for (int off = 16; off > 0; off >>= 1)
            acc[e] += __shfl_xor_sync(0xFFFFFFFFu, acc[e], off);
    }
    if (lane == 0) {
        float v[N_EXP];
#pragma unroll
        for (int e = 0; e < N_EXP; e++) v[e] = acc[e] + bg[e];
        int i0 = 0;
#pragma unroll
        for (int e = 1; e < N_EXP; e++) if (v[e] > v[i0]) i0 = e;
        int i1 = (i0 == 0) ? 1 : 0;
#pragma unroll
        for (int e = 0; e < N_EXP; e++)
            if (e != i0 && v[e] > v[i1]) i1 = e;
        float w0 = 1.0f / (1.0f + expf(v[i1] - v[i0]));
        float w1 = 1.0f - w0;
        int p0 = atomicAdd(&g_count[i0], 1);
        g_alist[i0 * T_TOK + p0] = warp * 2 + 0;
        g_wlist[i0 * T_TOK + p0] = w0;
        int p1 = atomicAdd(&g_count[i1], 1);
        g_alist[i1 * T_TOK + p1] = warp * 2 + 1;
        g_wlist[i1 * T_TOK + p1] = w1;
    }
}

// gather + pre-round to tf32
__global__ void gather_kernel(const float* __restrict__ x) {
    int pos = blockIdx.x;
    int e = blockIdx.y;
    if (pos >= g_count[e]) return;
    int tok = g_alist[e * T_TOK + pos] >> 1;
    const float4* src = (const float4*)(x + (size_t)tok * D_MODEL);
    float4* dst = (float4*)(g_Xg + ((size_t)e * T_TOK + pos) * D_MODEL);
    float4 v = src[threadIdx.x];
    v.x = f2tf32f(v.x); v.y = f2tf32f(v.y);
    v.z = f2tf32f(v.z); v.w = f2tf32f(v.w);
    dst[threadIdx.x] = v;
}

// ---------------- mma.sync tf32 grouped GEMM ----------------
// CTA tile 128x128, BK=32, 4 warps (128 threads), warp tile 64x64 (2x2 grid).
// 3-stage cp.async pipeline, ONE __syncthreads per chunk, 2 CTAs/SM.
#define BM 128
#define BN 128
#define BK 32
#define STAGES 3
#define A_LD 36
#define B_LD 136
#define A_FLOATS (BM * A_LD)            // 4608
#define B_FLOATS (BK * B_LD)            // 4352
#define BUF_FLOATS (A_FLOATS + B_FLOATS)
#define SMEM_DYN (STAGES * BUF_FLOATS * 4)   // 107520 bytes
#define NTHREADS 128

// MODE 0: H = tf32(relu(Xg @ w1 + b1))   (K=1024, NW=4096)
// MODE 1: Y = wgt * (H @ w2 + b2)        (K=4096, NW=1024)
template <int MODE>
__global__ void __launch_bounds__(NTHREADS, 2) moe_gemm(const float* __restrict__ W,
                                                        const float* __restrict__ bias) {
    constexpr int K  = MODE ? D_FF : D_MODEL;
    constexpr int NW = MODE ? D_MODEL : D_FF;
    constexpr int NC = K / BK;

    int e = blockIdx.z;
    int cnt = g_count[e];
    int m0 = blockIdx.y * BM;
    if (m0 >= cnt) return;
    int n0 = blockIdx.x * BN;

    const float* A  = (MODE ? g_H : g_Xg) + ((size_t)e * T_TOK + m0) * K;
    const float* Bw = W + (size_t)e * K * NW + n0;

    extern __shared__ __align__(16) float sm_f[];
    uint32_t sb = smem_u32(sm_f);

    int tid = threadIdx.x, lane = tid & 31, wid = tid >> 5;
    int wm = (wid >> 1) * 64;   // warp m offset: 0, 64
    int wn = (wid & 1) * 64;    // warp n offset: 0, 64
    int qrow = lane >> 2;
    int qcol = lane & 3;

    // A: 128 rows x 8 16B-units = 1024 units; B: 32 rows x 32 units = 1024 units
    auto load_chunk = [&](int c, int p) {
        uint32_t sA = sb + (uint32_t)p * (BUF_FLOATS * 4);
        uint32_t sB = sA + A_FLOATS * 4;
        int k0 = c * BK;
#pragma unroll
        for (int i = 0; i < 8; i++) {
            int idx = i * NTHREADS + tid;
            int m = idx >> 3, kq = idx & 7;
            cp16(sA + (uint32_t)m * (A_LD * 4) + (uint32_t)kq * 16,
                 A + (size_t)m * K + k0 + kq * 4);
        }
#pragma unroll
        for (int i = 0; i < 8; i++) {
            int idx = i * NTHREADS + tid;
            int k = idx >> 5, n16 = idx & 31;
            cp16(sB + (uint32_t)k * (B_LD * 4) + (uint32_t)n16 * 16,
                 Bw + (size_t)(k0 + k) * NW + n16 * 4);
        }
        asm volatile("cp.async.commit_group;" ::: "memory");
    };

    float acc[4][8][4];
#pragma unroll
    for (int mt = 0; mt < 4; mt++)
#pragma unroll
        for (int nt = 0; nt < 8; nt++)
#pragma unroll
            for (int q = 0; q < 4; q++) acc[mt][nt][q] = 0.f;

    load_chunk(0, 0);
    load_chunk(1, 1);

    for (int c = 0; c < NC; c++) {
        if (c + 1 < NC) asm volatile("cp.async.wait_group 1;" ::: "memory");
        else            asm volatile("cp.async.wait_group 0;" ::: "memory");
        __syncthreads();
        // stage (c+2)%3 held chunk c-1, consumed before the barrier -> safe to refill
        if (c + 2 < NC) load_chunk(c + 2, (c + 2) % STAGES);

        const float* As = sm_f + (size_t)(c % STAGES) * BUF_FLOATS;
        const float* Bs = As + A_FLOATS;

#pragma unroll
        for (int s = 0; s < 4; s++) {
            int kq = s * 8 + qcol;
            uint32_t af[4][4];
#pragma unroll
            for (int mt = 0; mt < 4; mt++) {
                int r = wm + mt * 16 + qrow;
                af[mt][0] = __float_as_uint(As[r * A_LD + kq]);          // pre-rounded
                af[mt][1] = __float_as_uint(As[(r + 8) * A_LD + kq]);
                af[mt][2] = __float_as_uint(As[r * A_LD + kq + 4]);
                af[mt][3] = __float_as_uint(As[(r + 8) * A_LD + kq + 4]);
            }
            uint32_t bf[8][2];
#pragma unroll
            for (int nt = 0; nt < 8; nt++) {
                int cn = wn + nt * 8 + qrow;
                bf[nt][0] = f2tf32(Bs[kq * B_LD + cn]);
                bf[nt][1] = f2tf32(Bs[(kq + 4) * B_LD + cn]);
            }
#pragma unroll
            for (int mt = 0; mt < 4; mt++)
#pragma unroll
                for (int nt = 0; nt < 8; nt++)
                    mma8(acc[mt][nt], af[mt], bf[nt]);
        }
    }

    // ---- epilogue ----
    const float* be = bias + (size_t)e * NW;
#pragma unroll
    for (int mt = 0; mt < 4; mt++) {
        int r0 = m0 + wm + mt * 16 + qrow;
        int r1 = r0 + 8;
        bool v0 = r0 < cnt, v1 = r1 < cnt;
        int aid0 = 0, aid1 = 0;
        float wg0 = 0.f, wg1 = 0.f;
        if (MODE == 1) {
            if (v0) { aid0 = g_alist[e * T_TOK + r0]; wg0 = g_wlist[e * T_TOK + r0]; }
            if (v1) { aid1 = g_alist[e * T_TOK + r1]; wg1 = g_wlist[e * T_TOK + r1]; }
        }
#pragma unroll
        for (int nt = 0; nt < 8; nt++) {
            int n = n0 + wn + nt * 8 + 2 * qcol;
            float2 b2 = *(const float2*)(be + n);
            float* cc = acc[mt][nt];
            if (v0) {
                float x0 = cc[0] + b2.x, x1 = cc[1] + b2.y;
                float2 o;
                if (MODE == 0) {
                    o.x = f2tf32f(x0 > 0.f ? x0 : 0.f);   // pre-round H for GEMM2
                    o.y = f2tf32f(x1 > 0.f ? x1 : 0.f);
                    *(float2*)(g_H + ((size_t)e * T_TOK + r0) * D_FF + n) = o;
                } else {
                    o.x = x0 * wg0; o.y = x1 * wg0;
                    *(float2*)(g_Y + (size_t)aid0 * D_MODEL + n) = o;
                }
            }
            if (v1) {
                float x2 = cc[2] + b2.x, x3 = cc[3] + b2.y;
                float2 o;
                if (MODE == 0) {
                    o.x = f2tf32f(x2 > 0.f ? x2 : 0.f);
                    o.y = f2tf32f(x3 > 0.f ? x3 : 0.f);
                    *(float2*)(g_H + ((size_t)e * T_TOK + r1) * D_FF + n) = o;
                } else {
                    o.x = x2 * wg1; o.y = x3 * wg1;
                    *(float2*)(g_Y + (size_t)aid1 * D_MODEL + n) = o;
                }
            }
        }
    }
}

// ---------------- combine: out[t] = Y[2t] + Y[2t+1] ----------------
__global__ void combine_kernel(float* __restrict__ out) {
    int i = blockIdx.x * blockDim.x + threadIdx.x;
    int total = T_TOK * D_MODEL / 4;
    if (i >= total) return;
    int t = (i * 4) >> 10;
    const float4* y0 = (const float4*)(g_Y + (size_t)(2 * t) * D_MODEL) + (i & 255);
    const float4* y1 = (const float4*)(g_Y + (size_t)(2 * t + 1) * D_MODEL) + (i & 255);
    float4 a = *y0, b = *y1;
    float4 r;
    r.x = a.x + b.x; r.y = a.y + b.y; r.z = a.z + b.z; r.w = a.w + b.w;
    ((float4*)out)[i] = r;
}

// ---------------- launch ----------------
extern "C" void kernel_launch(void* const* d_in, const int* in_sizes, int n_in,
                              void* d_out, int out_size) {
    const float* x   = (const float*)d_in[0];
    const float* wg  = (const float*)d_in[1];
    const float* bg  = (const float*)d_in[2];
    const float* w1  = (const float*)d_in[3];
    const float* b1  = (const float*)d_in[4];
    const float* w2  = (const float*)d_in[5];
    const float* b2  = (const float*)d_in[6];
    float* out = (float*)d_out;

    cudaFuncSetAttribute(moe_gemm<0>, cudaFuncAttributeMaxDynamicSharedMemorySize, SMEM_DYN);
    cudaFuncSetAttribute(moe_gemm<1>, cudaFuncAttributeMaxDynamicSharedMemorySize, SMEM_DYN);

    zero_counts_kernel<<<1, 32>>>();
    gate_kernel<<<(T_TOK * 32) / 256, 256>>>(x, wg, bg);

    dim3 gg(T_TOK, N_EXP);
    gather_kernel<<<gg, 256>>>(x);

    dim3 g1(D_FF / BN, T_TOK / BM, N_EXP);     // 32 x 16 x 8
    moe_gemm<0><<<g1, NTHREADS, SMEM_DYN>>>(w1, b1);

    dim3 g2(D_MODEL / BN, T_TOK / BM, N_EXP);  // 8 x 16 x 8
    moe_gemm<1><<<g2, NTHREADS, SMEM_DYN>>>(w2, b2);

    combine_kernel<<<(T_TOK * D_MODEL / 4 + 255) / 256, 256>>>(out);
}

// round 11
// speedup vs baseline: 5.1736x; 1.3151x over previous
#include <cuda_runtime.h>
#include <cuda_fp16.h>
#include <math.h>
#include <stdint.h>

#define T_TOK 2048
#define D_MODEL 1024
#define D_FF 4096
#define N_EXP 8

// ---------------- static scratch (no allocations allowed) ----------------
__device__ __half g_Hh[(size_t)N_EXP * T_TOK * D_FF];       // half activations [e][pos][ff]
__device__ __half g_Xh[(size_t)N_EXP * T_TOK * D_MODEL];    // gathered X rows, half
__device__ __half g_W1h[(size_t)N_EXP * D_FF * D_MODEL];    // w1 transposed: [e][n=ff][k=d]
__device__ __half g_W2h[(size_t)N_EXP * D_MODEL * D_FF];    // w2 transposed: [e][n=d][k=ff]
__device__ float  g_Y[(size_t)2 * T_TOK * D_MODEL];
__device__ int    g_alist[N_EXP * T_TOK];
__device__ float  g_wlist[N_EXP * T_TOK];
__device__ int    g_count[N_EXP];

// ---------------- helpers ----------------
__device__ __forceinline__ void cp16(uint32_t dst, const void* src) {
    asm volatile("cp.async.cg.shared.global [%0], [%1], 16;"
                 :: "r"(dst), "l"(src) : "memory");
}
__device__ __forceinline__ uint32_t smem_u32(const void* p) {
    uint32_t a;
    asm("{ .reg .u64 t; cvta.to.shared.u64 t, %1; cvt.u32.u64 %0, t; }"
        : "=r"(a) : "l"(p));
    return a;
}
__device__ __forceinline__ void mma16(float* c, const uint32_t* a, const uint32_t* b) {
    asm volatile(
        "mma.sync.aligned.m16n8k16.row.col.f32.f16.f16.f32 "
        "{%0,%1,%2,%3},{%4,%5,%6,%7},{%8,%9},{%0,%1,%2,%3};"
        : "+f"(c[0]), "+f"(c[1]), "+f"(c[2]), "+f"(c[3])
        : "r"(a[0]), "r"(a[1]), "r"(a[2]), "r"(a[3]), "r"(b[0]), "r"(b[1]));
}

// ---------------- small kernels ----------------
__global__ void zero_counts_kernel() {
    int i = threadIdx.x;
    if (i < N_EXP) g_count[i] = 0;
}

__global__ void gate_kernel(const float* __restrict__ x,
                            const float* __restrict__ wg,
                            const float* __restrict__ bg) {
    int warp = (blockIdx.x * blockDim.x + threadIdx.x) >> 5;
    int lane = threadIdx.x & 31;
    if (warp >= T_TOK) return;

    const float* xr = x + (size_t)warp * D_MODEL;
    float acc[N_EXP];
#pragma unroll
    for (int e = 0; e < N_EXP; e++) acc[e] = 0.f;
    for (int d = lane; d < D_MODEL; d += 32) {
        float xv = xr[d];
        const float* wr = wg + (size_t)d * N_EXP;
#pragma unroll
        for (int e = 0; e < N_EXP; e++) acc[e] += xv * wr[e];
    }
#pragma unroll
    for (int e = 0; e < N_EXP; e++) {
#pragma unroll
        for (int off = 16; off > 0; off >>= 1)
            acc[e] += __shfl_xor_sync(0xFFFFFFFFu, acc[e], off);
    }
    if (lane == 0) {
        float v[N_EXP];
#pragma unroll
        for (int e = 0; e < N_EXP; e++) v[e] = acc[e] + bg[e];
        int i0 = 0;
#pragma unroll
        for (int e = 1; e < N_EXP; e++) if (v[e] > v[i0]) i0 = e;
        int i1 = (i0 == 0) ? 1 : 0;
#pragma unroll
        for (int e = 0; e < N_EXP; e++)
            if (e != i0 && v[e] > v[i1]) i1 = e;
        float w0 = 1.0f / (1.0f + expf(v[i1] - v[i0]));
        float w1 = 1.0f - w0;
        int p0 = atomicAdd(&g_count[i0], 1);
        g_alist[i0 * T_TOK + p0] = warp * 2 + 0;
        g_wlist[i0 * T_TOK + p0] = w0;
        int p1 = atomicAdd(&g_count[i1], 1);
        g_alist[i1 * T_TOK + p1] = warp * 2 + 1;
        g_wlist[i1 * T_TOK + p1] = w1;
    }
}

// gather + convert to half
__global__ void gather_kernel(const float* __restrict__ x) {
    int pos = blockIdx.x;
    int e = blockIdx.y;
    if (pos >= g_count[e]) return;
    int tok = g_alist[e * T_TOK + pos] >> 1;
    const float4* src = (const float4*)(x + (size_t)tok * D_MODEL);
    float4 v = src[threadIdx.x];
    __half2 h01 = __floats2half2_rn(v.x, v.y);
    __half2 h23 = __floats2half2_rn(v.z, v.w);
    __half2* dst = (__half2*)(g_Xh + ((size_t)e * T_TOK + pos) * D_MODEL) + threadIdx.x * 2;
    dst[0] = h01;
    dst[1] = h23;
}

// transpose + convert: in [e][KD][ND] f32 -> out [e][ND][KD] half
template <int KD, int ND>
__global__ void __launch_bounds__(256) convt_kernel(const float* __restrict__ in,
                                                    __half* __restrict__ out) {
    __shared__ float s[32][33];
    int e = blockIdx.z;
    int kb = blockIdx.y * 32, nb = blockIdx.x * 32;
    int tx = threadIdx.x & 31, ty = threadIdx.x >> 5;   // ty 0..7
    const float* I = in + (size_t)e * KD * ND;
    __half* O = out + (size_t)e * ND * KD;
#pragma unroll
    for (int r = 0; r < 4; r++)
        s[ty + r * 8][tx] = I[(size_t)(kb + ty + r * 8) * ND + nb + tx];
    __syncthreads();
#pragma unroll
    for (int r = 0; r < 4; r++)
        O[(size_t)(nb + ty + r * 8) * KD + kb + tx] = __float2half_rn(s[tx][ty + r * 8]);
}

// ---------------- fp16 mma.sync grouped GEMM ----------------
// CTA 128x128, BK=64, 4 warps (2x2 grid of 64x64 warp tiles), 3-stage cp.async,
// 2 CTAs/SM. A [m][k] half row-major; B [n][k] half (pre-transposed) -> all
// fragments are contiguous half2 scalar LDS, conflict-free with LD=72.
#define BM 128
#define BN 128
#define BK 64
#define STAGES 3
#define LDH 72                          // halfs per padded smem row
#define ROW_B (LDH * 2)                 // 144 bytes
#define A_TILE_B (BM * ROW_B)           // 18432
#define B_TILE_B (BN * ROW_B)           // 18432
#define BUF_B (A_TILE_B + B_TILE_B)     // 36864
#define SMEM_DYN (STAGES * BUF_B)       // 110592
#define NTHREADS 128

// MODE 0: Hh = half(relu(Xh @ w1 + b1))   (K=1024, NW=4096, B=g_W1h)
// MODE 1: Y  = wgt * (Hh @ w2 + b2)       (K=4096, NW=1024, B=g_W2h)
template <int MODE>
__global__ void __launch_bounds__(NTHREADS, 2) moe_gemm(const __half* __restrict__ Bt,
                                                        const float* __restrict__ bias) {
    constexpr int K  = MODE ? D_FF : D_MODEL;
    constexpr int NW = MODE ? D_MODEL : D_FF;
    constexpr int NC = K / BK;

    int e = blockIdx.z;
    int cnt = g_count[e];
    int m0 = blockIdx.y * BM;
    if (m0 >= cnt) return;
    int n0 = blockIdx.x * BN;

    const __half* A  = (MODE ? g_Hh : g_Xh) + ((size_t)e * T_TOK + m0) * K;
    const __half* Bw = Bt + ((size_t)e * NW + n0) * K;

    extern __shared__ __align__(16) __half sm_h[];
    uint32_t sb = smem_u32(sm_h);

    int tid = threadIdx.x, lane = tid & 31, wid = tid >> 5;
    int wm = (wid >> 1) * 64;
    int wn = (wid & 1) * 64;
    int grp = lane >> 2;        // 0..7
    int c2  = (lane & 3) * 2;   // 0,2,4,6

    // A: 128 rows x 8 units(16B) = 1024; B: 128 rows x 8 units = 1024
    auto load_chunk = [&](int c, int p) {
        uint32_t sA = sb + (uint32_t)p * BUF_B;
        uint32_t sB = sA + A_TILE_B;
        int k0 = c * BK;
#pragma unroll
        for (int i = 0; i < 8; i++) {
            int idx = i * NTHREADS + tid;
            int m = idx >> 3, u = idx & 7;
            cp16(sA + (uint32_t)m * ROW_B + (uint32_t)u * 16,
                 A + (size_t)m * K + k0 + u * 8);
        }
#pragma unroll
        for (int i = 0; i < 8; i++) {
            int idx = i * NTHREADS + tid;
            int n = idx >> 3, u = idx & 7;
            cp16(sB + (uint32_t)n * ROW_B + (uint32_t)u * 16,
                 Bw + (size_t)n * K + k0 + u * 8);
        }
        asm volatile("cp.async.commit_group;" ::: "memory");
    };

    float acc[4][8][4];
#pragma unroll
    for (int mt = 0; mt < 4; mt++)
#pragma unroll
        for (int nt = 0; nt < 8; nt++)
#pragma unroll
            for (int q = 0; q < 4; q++) acc[mt][nt][q] = 0.f;

    load_chunk(0, 0);
    load_chunk(1, 1);

    for (int c = 0; c < NC; c++) {
        if (c + 1 < NC) asm volatile("cp.async.wait_group 1;" ::: "memory");
        else            asm volatile("cp.async.wait_group 0;" ::: "memory");
        __syncthreads();
        if (c + 2 < NC) load_chunk(c + 2, (c + 2) % STAGES);

        const __half* As = sm_h + (size_t)(c % STAGES) * (BUF_B / 2);
        const __half* Bs = As + (A_TILE_B / 2);

#pragma unroll
        for (int s = 0; s < 4; s++) {      // k16 steps within BK=64
            int kk = s * 16 + c2;
            uint32_t af[4][4];
#pragma unroll
            for (int mt = 0; mt < 4; mt++) {
                const __half* ap = As + (wm + mt * 16 + grp) * LDH + kk;
                af[mt][0] = *(const uint32_t*)(ap);
                af[mt][1] = *(const uint32_t*)(ap + 8 * LDH);
                af[mt][2] = *(const uint32_t*)(ap + 8);
                af[mt][3] = *(const uint32_t*)(ap + 8 * LDH + 8);
            }
            uint32_t bf[8][2];
#pragma unroll
            for (int nt = 0; nt < 8; nt++) {
                const __half* bp = Bs + (wn + nt * 8 + grp) * LDH + kk;
                bf[nt][0] = *(const uint32_t*)(bp);
                bf[nt][1] = *(const uint32_t*)(bp + 8);
            }
#pragma unroll
            for (int mt = 0; mt < 4; mt++)
#pragma unroll
                for (int nt = 0; nt < 8; nt++)
                    mma16(acc[mt][nt], af[mt], bf[nt]);
        }
    }

    // ---- epilogue ----
    const float* be = bias + (size_t)e * NW;
#pragma unroll
    for (int mt = 0; mt < 4; mt++) {
        int r0 = m0 + wm + mt * 16 + grp;
        int r1 = r0 + 8;
        bool v0 = r0 < cnt, v1 = r1 < cnt;
        int aid0 = 0, aid1 = 0;
        float wg0 = 0.f, wg1 = 0.f;
        if (MODE == 1) {
            if (v0) { aid0 = g_alist[e * T_TOK + r0]; wg0 = g_wlist[e * T_TOK + r0]; }
            if (v1) { aid1 = g_alist[e * T_TOK + r1]; wg1 = g_wlist[e * T_TOK + r1]; }
        }
#pragma unroll
        for (int nt = 0; nt < 8; nt++) {
            int n = n0 + wn + nt * 8 + c2;
            float2 b2 = *(const float2*)(be + n);
            float* cc = acc[mt][nt];
            if (v0) {
                float x0 = cc[0] + b2.x, x1 = cc[1] + b2.y;
                if (MODE == 0) {
                    x0 = x0 > 0.f ? x0 : 0.f;
                    x1 = x1 > 0.f ? x1 : 0.f;
                    *(__half2*)(g_Hh + ((size_t)e * T_TOK + r0) * D_FF + n) =
                        __floats2half2_rn(x0, x1);
                } else {
                    float2 o; o.x = x0 * wg0; o.y = x1 * wg0;
                    *(float2*)(g_Y + (size_t)aid0 * D_MODEL + n) = o;
                }
            }
            if (v1) {
                float x2 = cc[2] + b2.x, x3 = cc[3] + b2.y;
                if (MODE == 0) {
                    x2 = x2 > 0.f ? x2 : 0.f;
                    x3 = x3 > 0.f ? x3 : 0.f;
                    *(__half2*)(g_Hh + ((size_t)e * T_TOK + r1) * D_FF + n) =
                        __floats2half2_rn(x2, x3);
                } else {
                    float2 o; o.x = x2 * wg1; o.y = x3 * wg1;
                    *(float2*)(g_Y + (size_t)aid1 * D_MODEL + n) = o;
                }
            }
        }
    }
}

// ---------------- combine: out[t] = Y[2t] + Y[2t+1] ----------------
__global__ void combine_kernel(float* __restrict__ out) {
    int i = blockIdx.x * blockDim.x + threadIdx.x;
    int total = T_TOK * D_MODEL / 4;
    if (i >= total) return;
    int t = (i * 4) >> 10;
    const float4* y0 = (const float4*)(g_Y + (size_t)(2 * t) * D_MODEL) + (i & 255);
    const float4* y1 = (const float4*)(g_Y + (size_t)(2 * t + 1) * D_MODEL) + (i & 255);
    float4 a = *y0, b = *y1;
    float4 r;
    r.x = a.x + b.x; r.y = a.y + b.y; r.z = a.z + b.z; r.w = a.w + b.w;
    ((float4*)out)[i] = r;
}

// ---------------- launch ----------------
extern "C" void kernel_launch(void* const* d_in, const int* in_sizes, int n_in,
                              void* d_out, int out_size) {
    const float* x   = (const float*)d_in[0];
    const float* wg  = (const float*)d_in[1];
    const float* bg  = (const float*)d_in[2];
    const float* w1  = (const float*)d_in[3];
    const float* b1  = (const float*)d_in[4];
    const float* w2  = (const float*)d_in[5];
    const float* b2  = (const float*)d_in[6];
    float* out = (float*)d_out;

    cudaFuncSetAttribute(moe_gemm<0>, cudaFuncAttributeMaxDynamicSharedMemorySize, SMEM_DYN);
    cudaFuncSetAttribute(moe_gemm<1>, cudaFuncAttributeMaxDynamicSharedMemorySize, SMEM_DYN);

    __half* w1h; cudaGetSymbolAddress((void**)&w1h, g_W1h);
    __half* w2h; cudaGetSymbolAddress((void**)&w2h, g_W2h);

    zero_counts_kernel<<<1, 32>>>();
    gate_kernel<<<(T_TOK * 32) / 256, 256>>>(x, wg, bg);

    // weight convert+transpose (independent of gating)
    dim3 c1(D_FF / 32, D_MODEL / 32, N_EXP);   // 128 x 32 x 8
    convt_kernel<D_MODEL, D_FF><<<c1, 256>>>(w1, w1h);
    dim3 c2g(D_MODEL / 32, D_FF / 32, N_EXP);  // 32 x 128 x 8
    convt_kernel<D_FF, D_MODEL><<<c2g, 256>>>(w2, w2h);

    dim3 gg(T_TOK, N_EXP);
    gather_kernel<<<gg, 256>>>(x);

    dim3 g1(D_FF / BN, T_TOK / BM, N_EXP);     // 32 x 16 x 8
    moe_gemm<0><<<g1, NTHREADS, SMEM_DYN>>>(w1h, b1);

    dim3 g2(D_MODEL / BN, T_TOK / BM, N_EXP);  // 8 x 16 x 8
    moe_gemm<1><<<g2, NTHREADS, SMEM_DYN>>>(w2h, b2);

    combine_kernel<<<(T_TOK * D_MODEL / 4 + 255) / 256, 256>>>(out);
}

// round 14
// speedup vs baseline: 5.6716x; 1.0962x over previous
#include <cuda_runtime.h>
#include <cuda_fp16.h>
#include <math.h>
#include <stdint.h>

#define T_TOK 2048
#define D_MODEL 1024
#define D_FF 4096
#define N_EXP 8

// ---------------- static scratch (no allocations allowed) ----------------
__device__ __half g_Hh[(size_t)N_EXP * T_TOK * D_FF];       // half activations [e][pos][ff]
__device__ __half g_Xh[(size_t)N_EXP * T_TOK * D_MODEL];    // gathered X rows, half
__device__ __half g_W1h[(size_t)N_EXP * D_MODEL * D_FF];    // w1 as-is: [e][k=d][n=ff], half
__device__ __half g_W2h[(size_t)N_EXP * D_FF * D_MODEL];    // w2 as-is: [e][k=ff][n=d], half
__device__ float  g_Y[(size_t)2 * T_TOK * D_MODEL];
__device__ int    g_alist[N_EXP * T_TOK];
__device__ float  g_wlist[N_EXP * T_TOK];
__device__ int    g_count[N_EXP];

// ---------------- helpers ----------------
__device__ __forceinline__ void cp16(uint32_t dst, const void* src) {
    asm volatile("cp.async.cg.shared.global [%0], [%1], 16;"
                 :: "r"(dst), "l"(src) : "memory");
}
__device__ __forceinline__ uint32_t smem_u32(const void* p) {
    uint32_t a;
    asm("{ .reg .u64 t; cvta.to.shared.u64 t, %1; cvt.u32.u64 %0, t; }"
        : "=r"(a) : "l"(p));
    return a;
}
__device__ __forceinline__ void ldsm4(uint32_t& r0, uint32_t& r1, uint32_t& r2, uint32_t& r3,
                                      uint32_t addr) {
    asm volatile("ldmatrix.sync.aligned.m8n8.x4.shared.b16 {%0,%1,%2,%3}, [%4];"
                 : "=r"(r0), "=r"(r1), "=r"(r2), "=r"(r3) : "r"(addr));
}
__device__ __forceinline__ void ldsm4t(uint32_t& r0, uint32_t& r1, uint32_t& r2, uint32_t& r3,
                                       uint32_t addr) {
    asm volatile("ldmatrix.sync.aligned.m8n8.x4.trans.shared.b16 {%0,%1,%2,%3}, [%4];"
                 : "=r"(r0), "=r"(r1), "=r"(r2), "=r"(r3) : "r"(addr));
}
__device__ __forceinline__ void mma16(float* c, const uint32_t* a, const uint32_t* b) {
    asm volatile(
        "mma.sync.aligned.m16n8k16.row.col.f32.f16.f16.f32 "
        "{%0,%1,%2,%3},{%4,%5,%6,%7},{%8,%9},{%0,%1,%2,%3};"
        : "+f"(c[0]), "+f"(c[1]), "+f"(c[2]), "+f"(c[3])
        : "r"(a[0]), "r"(a[1]), "r"(a[2]), "r"(a[3]), "r"(b[0]), "r"(b[1]));
}

// ---------------- small kernels ----------------
__global__ void zero_counts_kernel() {
    int i = threadIdx.x;
    if (i < N_EXP) g_count[i] = 0;
}

__global__ void gate_kernel(const float* __restrict__ x,
                            const float* __restrict__ wg,
                            const float* __restrict__ bg) {
    int warp = (blockIdx.x * blockDim.x + threadIdx.x) >> 5;
    int lane = threadIdx.x & 31;
    if (warp >= T_TOK) return;

    const float* xr = x + (size_t)warp * D_MODEL;
    float acc[N_EXP];
#pragma unroll
    for (int e = 0; e < N_EXP; e++) acc[e] = 0.f;
    for (int d = lane; d < D_MODEL; d += 32) {
        float xv = xr[d];
        const float* wr = wg + (size_t)d * N_EXP;
#pragma unroll
        for (int e = 0; e < N_EXP; e++) acc[e] += xv * wr[e];
    }
#pragma unroll
    for (int e = 0; e < N_EXP; e++) {
#pragma unroll
        for (int off = 16; off > 0; off >>= 1)
            acc[e] += __shfl_xor_sync(0xFFFFFFFFu, acc[e], off);
    }
    if (lane == 0) {
        float v[N_EXP];
#pragma unroll
        for (int e = 0; e < N_EXP; e++) v[e] = acc[e] + bg[e];
        int i0 = 0;
#pragma unroll
        for (int e = 1; e < N_EXP; e++) if (v[e] > v[i0]) i0 = e;
        int i1 = (i0 == 0) ? 1 : 0;
#pragma unroll
        for (int e = 0; e < N_EXP; e++)
            if (e != i0 && v[e] > v[i1]) i1 = e;
        float w0 = 1.0f / (1.0f + expf(v[i1] - v[i0]));
        float w1 = 1.0f - w0;
        int p0 = atomicAdd(&g_count[i0], 1);
        g_alist[i0 * T_TOK + p0] = warp * 2 + 0;
        g_wlist[i0 * T_TOK + p0] = w0;
        int p1 = atomicAdd(&g_count[i1], 1);
        g_alist[i1 * T_TOK + p1] = warp * 2 + 1;
        g_wlist[i1 * T_TOK + p1] = w1;
    }
}

// gather + convert to half
__global__ void gather_kernel(const float* __restrict__ x) {
    int pos = blockIdx.x;
    int e = blockIdx.y;
    if (pos >= g_count[e]) return;
    int tok = g_alist[e * T_TOK + pos] >> 1;
    const float4* src = (const float4*)(x + (size_t)tok * D_MODEL);
    float4 v = src[threadIdx.x];
    __half2* dst = (__half2*)(g_Xh + ((size_t)e * T_TOK + pos) * D_MODEL) + threadIdx.x * 2;
    dst[0] = __floats2half2_rn(v.x, v.y);
    dst[1] = __floats2half2_rn(v.z, v.w);
}

// streaming f32 -> f16 convert (no transpose)
__global__ void __launch_bounds__(256) conv_kernel(const float4* __restrict__ in,
                                                   __half2* __restrict__ out, int n4) {
    int i = blockIdx.x * blockDim.x + threadIdx.x;
    if (i >= n4) return;
    float4 v = in[i];
    out[2 * i + 0] = __floats2half2_rn(v.x, v.y);
    out[2 * i + 1] = __floats2half2_rn(v.z, v.w);
}

// ---------------- fp16 mma.sync grouped GEMM (ldmatrix fragments) ----------------
// CTA 128x128, BK=64, 4 warps (2x2 grid of 64x64 warp tiles), 3-stage cp.async,
// 2 CTAs/SM. A smem [m][k] pitch 144B (9x16B units); B smem [k][n] pitch 272B
// (17 units) read via ldmatrix.trans. Both conflict-free by pitch.
#define BM 128
#define BN 128
#define BK 64
#define STAGES 3
#define A_PITCH 144                      // bytes per A row (64 halfs + pad)
#define B_PITCH 272                      // bytes per B k-row (128 halfs + pad)
#define A_TILE_B (BM * A_PITCH)          // 18432
#define B_TILE_B (BK * B_PITCH)          // 17408
#define BUF_B (A_TILE_B + B_TILE_B)      // 35840
#define SMEM_DYN (STAGES * BUF_B)        // 107520
#define NTHREADS 128

// MODE 0: Hh = half(relu(Xh @ w1 + b1))   (K=1024, NW=4096, B=g_W1h)
// MODE 1: Y  = wgt * (Hh @ w2 + b2)       (K=4096, NW=1024, B=g_W2h)
template <int MODE>
__global__ void __launch_bounds__(NTHREADS, 2) moe_gemm(const __half* __restrict__ Wh,
                                                        const float* __restrict__ bias) {
    constexpr int K  = MODE ? D_FF : D_MODEL;
    constexpr int NW = MODE ? D_MODEL : D_FF;
    constexpr int NC = K / BK;

    int e = blockIdx.z;
    int cnt = g_count[e];
    int m0 = blockIdx.y * BM;
    if (m0 >= cnt) return;
    int n0 = blockIdx.x * BN;

    const __half* A  = (MODE ? g_Hh : g_Xh) + ((size_t)e * T_TOK + m0) * K;
    const __half* Bw = Wh + (size_t)e * K * NW + n0;

    extern __shared__ __align__(16) __half sm_h[];
    uint32_t sb = smem_u32(sm_h);

    int tid = threadIdx.x, lane = tid & 31, wid = tid >> 5;
    int wm = (wid >> 1) * 64;
    int wn = (wid & 1) * 64;
    int grp = lane >> 2;        // epilogue row within 8-group
    int c2  = (lane & 3) * 2;   // epilogue col pair

    // ldmatrix lane addressing
    int which = lane >> 3;      // 0..3
    int lr    = lane & 7;       // row within 8x8 tile
    // A x4: matrix w: row = wm + mt*16 + (w&1)*8 + lr, colhalf = s*16 + (w>>1)*8
    uint32_t aLane = (uint32_t)(wm + (which & 1) * 8 + lr) * A_PITCH
                   + (uint32_t)(which >> 1) * 16;
    // B x4.trans: matrix w: k-row = s*16 + (w&1)*8 + lr, n = wn + pair*16 + (w>>1)*8
    uint32_t bLane = (uint32_t)((which & 1) * 8 + lr) * B_PITCH
                   + (uint32_t)(wn + (which >> 1) * 8) * 2;

    // A: 128 rows x 8 units = 1024; B: 64 k-rows x 16 units = 1024
    auto load_chunk = [&](int c, int p) {
        uint32_t sA = sb + (uint32_t)p * BUF_B;
        uint32_t sB = sA + A_TILE_B;
        int k0 = c * BK;
#pragma unroll
        for (int i = 0; i < 8; i++) {
            int idx = i * NTHREADS + tid;
            int m = idx >> 3, u = idx & 7;
            cp16(sA + (uint32_t)m * A_PITCH + (uint32_t)u * 16,
                 A + (size_t)m * K + k0 + u * 8);
        }
#pragma unroll
        for (int i = 0; i < 8; i++) {
            int idx = i * NTHREADS + tid;
            int k = idx >> 4, u = idx & 15;
            cp16(sB + (uint32_t)k * B_PITCH + (uint32_t)u * 16,
                 Bw + (size_t)(k0 + k) * NW + u * 8);
        }
        asm volatile("cp.async.commit_group;" ::: "memory");
    };

    float acc[4][8][4];
#pragma unroll
    for (int mt = 0; mt < 4; mt++)
#pragma unroll
        for (int nt = 0; nt < 8; nt++)
#pragma unroll
            for (int q = 0; q < 4; q++) acc[mt][nt][q] = 0.f;

    load_chunk(0, 0);
    load_chunk(1, 1);

    for (int c = 0; c < NC; c++) {
        if (c + 1 < NC) asm volatile("cp.async.wait_group 1;" ::: "memory");
        else            asm volatile("cp.async.wait_group 0;" ::: "memory");
        __syncthreads();
        if (c + 2 < NC) load_chunk(c + 2, (c + 2) % STAGES);

        uint32_t stA = sb + (uint32_t)(c % STAGES) * BUF_B + aLane;
        uint32_t stB = sb + (uint32_t)(c % STAGES) * BUF_B + A_TILE_B + bLane;

#pragma unroll
        for (int s = 0; s < 4; s++) {          // k16 steps within BK=64
            uint32_t aS = stA + (uint32_t)s * 32;            // +16 halfs
            uint32_t bS = stB + (uint32_t)s * (16 * B_PITCH);
            uint32_t af[4][4];
#pragma unroll
            for (int mt = 0; mt < 4; mt++)
                ldsm4(af[mt][0], af[mt][1], af[mt][2], af[mt][3],
                      aS + (uint32_t)mt * (16 * A_PITCH));
            uint32_t bf[8][2];
#pragma unroll
            for (int p = 0; p < 4; p++)
                ldsm4t(bf[2 * p][0], bf[2 * p][1], bf[2 * p + 1][0], bf[2 * p + 1][1],
                       bS + (uint32_t)p * 32);               // +16 n-halfs
#pragma unroll
            for (int mt = 0; mt < 4; mt++)
#pragma unroll
                for (int nt = 0; nt < 8; nt++)
                    mma16(acc[mt][nt], af[mt], bf[nt]);
        }
    }

    // ---- epilogue (fragment layout unchanged) ----
    const float* be = bias + (size_t)e * NW;
#pragma unroll
    for (int mt = 0; mt < 4; mt++) {
        int r0 = m0 + wm + mt * 16 + grp;
        int r1 = r0 + 8;
        bool v0 = r0 < cnt, v1 = r1 < cnt;
        int aid0 = 0, aid1 = 0;
        float wg0 = 0.f, wg1 = 0.f;
        if (MODE == 1) {
            if (v0) { aid0 = g_alist[e * T_TOK + r0]; wg0 = g_wlist[e * T_TOK + r0]; }
            if (v1) { aid1 = g_alist[e * T_TOK + r1]; wg1 = g_wlist[e * T_TOK + r1]; }
        }
#pragma unroll
        for (int nt = 0; nt < 8; nt++) {
            int n = n0 + wn + nt * 8 + c2;
            float2 b2 = *(const float2*)(be + n);
            float* cc = acc[mt][nt];
            if (v0) {
                float x0 = cc[0] + b2.x, x1 = cc[1] + b2.y;
                if (MODE == 0) {
                    x0 = x0 > 0.f ? x0 : 0.f;
                    x1 = x1 > 0.f ? x1 : 0.f;
                    *(__half2*)(g_Hh + ((size_t)e * T_TOK + r0) * D_FF + n) =
                        __floats2half2_rn(x0, x1);
                } else {
                    float2 o; o.x = x0 * wg0; o.y = x1 * wg0;
                    *(float2*)(g_Y + (size_t)aid0 * D_MODEL + n) = o;
                }
            }
            if (v1) {
                float x2 = cc[2] + b2.x, x3 = cc[3] + b2.y;
                if (MODE == 0) {
                    x2 = x2 > 0.f ? x2 : 0.f;
                    x3 = x3 > 0.f ? x3 : 0.f;
                    *(__half2*)(g_Hh + ((size_t)e * T_TOK + r1) * D_FF + n) =
                        __floats2half2_rn(x2, x3);
                } else {
                    float2 o; o.x = x2 * wg1; o.y = x3 * wg1;
                    *(float2*)(g_Y + (size_t)aid1 * D_MODEL + n) = o;
                }
            }
        }
    }
}

// ---------------- combine: out[t] = Y[2t] + Y[2t+1] ----------------
__global__ void combine_kernel(float* __restrict__ out) {
    int i = blockIdx.x * blockDim.x + threadIdx.x;
    int total = T_TOK * D_MODEL / 4;
    if (i >= total) return;
    int t = (i * 4) >> 10;
    const float4* y0 = (const float4*)(g_Y + (size_t)(2 * t) * D_MODEL) + (i & 255);
    const float4* y1 = (const float4*)(g_Y + (size_t)(2 * t + 1) * D_MODEL) + (i & 255);
    float4 a = *y0, b = *y1;
    float4 r;
    r.x = a.x + b.x; r.y = a.y + b.y; r.z = a.z + b.z; r.w = a.w + b.w;
    ((float4*)out)[i] = r;
}

// ---------------- launch ----------------
extern "C" void kernel_launch(void* const* d_in, const int* in_sizes, int n_in,
                              void* d_out, int out_size) {
    const float* x   = (const float*)d_in[0];
    const float* wg  = (const float*)d_in[1];
    const float* bg  = (const float*)d_in[2];
    const float* w1  = (const float*)d_in[3];
    const float* b1  = (const float*)d_in[4];
    const float* w2  = (const float*)d_in[5];
    const float* b2  = (const float*)d_in[6];
    float* out = (float*)d_out;

    cudaFuncSetAttribute(moe_gemm<0>, cudaFuncAttributeMaxDynamicSharedMemorySize, SMEM_DYN);
    cudaFuncSetAttribute(moe_gemm<1>, cudaFuncAttributeMaxDynamicSharedMemorySize, SMEM_DYN);

    __half* w1h; cudaGetSymbolAddress((void**)&w1h, g_W1h);
    __half* w2h; cudaGetSymbolAddress((void**)&w2h, g_W2h);

    zero_counts_kernel<<<1, 32>>>();
    gate_kernel<<<(T_TOK * 32) / 256, 256>>>(x, wg, bg);

    // streaming weight converts (no transpose needed with ldmatrix.trans)
    int n4 = (N_EXP * D_MODEL * D_FF) / 4;   // 8388608 float4 per weight tensor
    conv_kernel<<<(n4 + 255) / 256, 256>>>((const float4*)w1, (__half2*)w1h, n4);
    conv_kernel<<<(n4 + 255) / 256, 256>>>((const float4*)w2, (__half2*)w2h, n4);

    dim3 gg(T_TOK, N_EXP);
    gather_kernel<<<gg, 256>>>(x);

    dim3 g1(D_FF / BN, T_TOK / BM, N_EXP);     // 32 x 16 x 8
    moe_gemm<0><<<g1, NTHREADS, SMEM_DYN>>>(w1h, b1);

    dim3 g2(D_MODEL / BN, T_TOK / BM, N_EXP);  // 8 x 16 x 8
    moe_gemm<1><<<g2, NTHREADS, SMEM_DYN>>>(w2h, b2);

    combine_kernel<<<(T_TOK * D_MODEL / 4 + 255) / 256, 256>>>(out);
}